// round 3
// baseline (speedup 1.0000x reference)
#include <cuda_runtime.h>
#include <cuda_bf16.h>
#include <math.h>
#include <stdint.h>

#define B_   2
#define T_   2048
#define D_   1024
#define NH_  16
#define HD_  64
#define BT_  (B_*T_)      // 4096
#define NDH_ (NH_*HD_)    // 1024

// Scratch (allocation-free: __device__ globals)
__device__ float g_q[(size_t)B_*NH_*T_*HD_];     // [b,n,t,h]
__device__ float g_k[(size_t)B_*NH_*T_*HD_];     // [b,n,t,h]
__device__ float g_v[(size_t)B_*NH_*T_*HD_];     // [b,n,t,h]
__device__ float g_attn[(size_t)BT_*NDH_];       // [b,t,n,h] == [4096, 1024]
__device__ float g_wpt[(size_t)NDH_*D_];         // [(n,h), d]

// ---------------------------------------------------------------------------
// helpers
// ---------------------------------------------------------------------------
__device__ __forceinline__ uint32_t f2tf32(float x) {
    uint32_t r;
    asm("cvt.rna.tf32.f32 %0, %1;" : "=r"(r) : "f"(x));
    return r;
}

__device__ __forceinline__ void mma_tf32(float* c,
                                         uint32_t a0, uint32_t a1, uint32_t a2, uint32_t a3,
                                         uint32_t b0, uint32_t b1) {
    asm volatile("mma.sync.aligned.m16n8k8.row.col.f32.tf32.tf32.f32 "
                 "{%0,%1,%2,%3}, {%4,%5,%6,%7}, {%8,%9}, {%0,%1,%2,%3};"
                 : "+f"(c[0]), "+f"(c[1]), "+f"(c[2]), "+f"(c[3])
                 : "r"(a0), "r"(a1), "r"(a2), "r"(a3), "r"(b0), "r"(b1));
}

__device__ __forceinline__ void mma_bf16(float* c,
                                         uint32_t a0, uint32_t a1, uint32_t a2, uint32_t a3,
                                         uint32_t b0, uint32_t b1) {
    asm volatile("mma.sync.aligned.m16n8k16.row.col.f32.bf16.bf16.f32 "
                 "{%0,%1,%2,%3}, {%4,%5,%6,%7}, {%8,%9}, {%0,%1,%2,%3};"
                 : "+f"(c[0]), "+f"(c[1]), "+f"(c[2]), "+f"(c[3])
                 : "r"(a0), "r"(a1), "r"(a2), "r"(a3), "r"(b0), "r"(b1));
}

// split two fp32 (even,odd along k) into packed bf16x2 hi and lo parts
__device__ __forceinline__ void split2(float e, float o, uint32_t& hi, uint32_t& lo) {
    __nv_bfloat162 h = __floats2bfloat162_rn(e, o);
    float he = __low2float(h), ho = __high2float(h);
    __nv_bfloat162 l = __floats2bfloat162_rn(e - he, o - ho);
    hi = *reinterpret_cast<uint32_t*>(&h);
    lo = *reinterpret_cast<uint32_t*>(&l);
}

// ---------------------------------------------------------------------------
// Transpose w_projection [N, D, H] -> [(n,h), d]
// ---------------------------------------------------------------------------
__global__ void transpose_wp_kernel(const float* __restrict__ wp,
                                    float* __restrict__ wpt)
{
    int idx = blockIdx.x * blockDim.x + threadIdx.x;
    if (idx >= NDH_ * D_) return;
    int d = idx % D_;
    int k = idx / D_;          // k = n*H + h
    int n = k / HD_;
    int h = k % HD_;
    wpt[idx] = wp[((size_t)n * D_ + d) * HD_ + h];
}

// ---------------------------------------------------------------------------
// bf16-split tensor-core GEMM: C = A[M,K] * B[K,N] + bias, near-fp32 accuracy.
// 128x128 block tile, BK=16, 256 threads = 8 warps (4 M x 2 N), warp 32x64.
// MODE 0: C -> [B, N, T, H];  MODE 1: C -> [M, Ncols] row-major.
// ---------------------------------------------------------------------------
template<int MODE>
__global__ __launch_bounds__(256)
void gemm_bf16x2_kernel(const float* __restrict__ A,
                        const float* __restrict__ Bm,
                        const float* __restrict__ bias,
                        float* __restrict__ C,
                        int M, int K, int Ncols)
{
    __shared__ uint32_t AsHi[8][136];
    __shared__ uint32_t AsLo[8][136];
    __shared__ uint32_t BsHi[8][136];
    __shared__ uint32_t BsLo[8][136];

    const int tid  = threadIdx.x;
    const int warp = tid >> 5;
    const int lane = tid & 31;
    const int g    = lane >> 2;
    const int tig  = lane & 3;
    const int wm   = warp >> 1;   // 0..3
    const int wn   = warp & 1;    // 0..1
    const int m0   = blockIdx.y * 128;
    const int n0   = blockIdx.x * 128;

    const int la_m    = tid >> 1;        // 0..127
    const int la_half = tid & 1;         // k-half: 0 or 1 (8 floats each)
    const int lb_pr   = tid >> 5;        // 0..7 (pair-row)
    const int lb_n4   = (tid & 31) << 2; // 0..124

    float acc[2][8][4];
    #pragma unroll
    for (int i = 0; i < 2; i++)
        #pragma unroll
        for (int j = 0; j < 8; j++)
            #pragma unroll
            for (int e = 0; e < 4; e++)
                acc[i][j][e] = 0.0f;

    for (int k0 = 0; k0 < K; k0 += 16) {
        __syncthreads();
        // ---- load A tile: rows m0..m0+127, k0..k0+15, packed pairs along k
        {
            const float4* ap = (const float4*)(A + (size_t)(m0 + la_m) * K + k0 + la_half * 8);
            float4 r0 = ap[0];
            float4 r1 = ap[1];
            uint32_t h, l;
            const int pr = la_half * 4;
            split2(r0.x, r0.y, h, l); AsHi[pr + 0][la_m] = h; AsLo[pr + 0][la_m] = l;
            split2(r0.z, r0.w, h, l); AsHi[pr + 1][la_m] = h; AsLo[pr + 1][la_m] = l;
            split2(r1.x, r1.y, h, l); AsHi[pr + 2][la_m] = h; AsLo[pr + 2][la_m] = l;
            split2(r1.z, r1.w, h, l); AsHi[pr + 3][la_m] = h; AsLo[pr + 3][la_m] = l;
        }
        // ---- load B tile: rows k0..k0+15, cols n0..n0+127
        {
            const float* bp = Bm + (size_t)(k0 + 2 * lb_pr) * Ncols + n0 + lb_n4;
            float4 r0 = *(const float4*)bp;
            float4 r1 = *(const float4*)(bp + Ncols);
            uint32_t h0, l0, h1, l1, h2, l2, h3, l3;
            split2(r0.x, r1.x, h0, l0);
            split2(r0.y, r1.y, h1, l1);
            split2(r0.z, r1.z, h2, l2);
            split2(r0.w, r1.w, h3, l3);
            *(uint4*)&BsHi[lb_pr][lb_n4] = make_uint4(h0, h1, h2, h3);
            *(uint4*)&BsLo[lb_pr][lb_n4] = make_uint4(l0, l1, l2, l3);
        }
        __syncthreads();

        // ---- fragments + mma
        uint32_t bh[8][2], bl[8][2];
        #pragma unroll
        for (int nt = 0; nt < 8; nt++) {
            const int col = wn * 64 + nt * 8 + g;
            bh[nt][0] = BsHi[tig][col];     bh[nt][1] = BsHi[tig + 4][col];
            bl[nt][0] = BsLo[tig][col];     bl[nt][1] = BsLo[tig + 4][col];
        }
        #pragma unroll
        for (int mt = 0; mt < 2; mt++) {
            const int rb = wm * 32 + mt * 16;
            uint32_t ah0 = AsHi[tig][rb + g],     ah1 = AsHi[tig][rb + g + 8];
            uint32_t ah2 = AsHi[tig + 4][rb + g], ah3 = AsHi[tig + 4][rb + g + 8];
            uint32_t al0 = AsLo[tig][rb + g],     al1 = AsLo[tig][rb + g + 8];
            uint32_t al2 = AsLo[tig + 4][rb + g], al3 = AsLo[tig + 4][rb + g + 8];
            #pragma unroll
            for (int nt = 0; nt < 8; nt++) {
                mma_bf16(acc[mt][nt], ah0, ah1, ah2, ah3, bh[nt][0], bh[nt][1]);
                mma_bf16(acc[mt][nt], ah0, ah1, ah2, ah3, bl[nt][0], bl[nt][1]);
                mma_bf16(acc[mt][nt], al0, al1, al2, al3, bh[nt][0], bh[nt][1]);
            }
        }
    }

    // ---- epilogue
    #pragma unroll
    for (int mt = 0; mt < 2; mt++) {
        #pragma unroll
        for (int nt = 0; nt < 8; nt++) {
            const int cbase = n0 + wn * 64 + nt * 8 + tig * 2;
            #pragma unroll
            for (int e = 0; e < 4; e++) {
                const int m  = m0 + wm * 32 + mt * 16 + g + ((e >= 2) ? 8 : 0);
                const int cc = cbase + (e & 1);
                float val = acc[mt][nt][e] + bias[cc];
                if (MODE == 0) {
                    int b = m / T_, t = m % T_;
                    int n = cc >> 6, h = cc & 63;
                    C[(((size_t)b * NH_ + n) * T_ + t) * HD_ + h] = val;
                } else {
                    C[(size_t)m * Ncols + cc] = val;
                }
            }
        }
    }
}

// ---------------------------------------------------------------------------
// tf32 tensor-core flash attention.
// Block = 128 threads (4 warps), handles 64 query rows of one (b, head).
// Each warp owns 16 rows. KV tiles of 64 keys; K buffer is reused for P.
// Output written to [b, t, n, h].
// ---------------------------------------------------------------------------
__global__ __launch_bounds__(128)
void attn_tc_kernel(const float* __restrict__ Q,
                    const float* __restrict__ K,
                    const float* __restrict__ V,
                    float* __restrict__ O)
{
    __shared__ float KP[64][68];   // K tile (tf32 bits), reused for P
    __shared__ float Vs[64][72];   // V tile (tf32 bits)

    const int tid  = threadIdx.x;
    const int warp = tid >> 5;
    const int lane = tid & 31;
    const int g    = lane >> 2;
    const int tig  = lane & 3;
    const int bn   = blockIdx.y;        // b*NH + n
    const int b    = bn / NH_;
    const int n    = bn % NH_;
    const int q0   = blockIdx.x * 64;
    const int wrow = warp * 16;

    const float* Qg = Q + ((size_t)bn * T_ + q0) * HD_;
    const float* Kg = K + (size_t)bn * T_ * HD_;
    const float* Vg = V + (size_t)bn * T_ * HD_;

    // ---- stage Q tile into KP, then load persistent A-fragments (prescaled)
    #pragma unroll
    for (int i = 0; i < 8; i++) {
        int lin = tid + i * 128;          // float4 slots over 64x16
        int r = lin >> 4, c4 = (lin & 15) << 2;
        float4 v4 = *(const float4*)(Qg + r * HD_ + c4);
        KP[r][c4 + 0] = v4.x; KP[r][c4 + 1] = v4.y;
        KP[r][c4 + 2] = v4.z; KP[r][c4 + 3] = v4.w;
    }
    __syncthreads();
    uint32_t qf[8][4];
    const float qscale = 0.125f;          // 1/sqrt(64)
    #pragma unroll
    for (int k8 = 0; k8 < 8; k8++) {
        qf[k8][0] = f2tf32(KP[wrow + g    ][k8 * 8 + tig    ] * qscale);
        qf[k8][1] = f2tf32(KP[wrow + g + 8][k8 * 8 + tig    ] * qscale);
        qf[k8][2] = f2tf32(KP[wrow + g    ][k8 * 8 + tig + 4] * qscale);
        qf[k8][3] = f2tf32(KP[wrow + g + 8][k8 * 8 + tig + 4] * qscale);
    }

    float of[8][4];
    #pragma unroll
    for (int i = 0; i < 8; i++)
        #pragma unroll
        for (int e = 0; e < 4; e++) of[i][e] = 0.0f;
    float m0r = -1e30f, m1r = -1e30f;
    float l0r = 0.0f,   l1r = 0.0f;

    for (int s0 = 0; s0 < T_; s0 += 64) {
        __syncthreads();   // previous tile's P/V reads complete
        // ---- load K -> KP, V -> Vs (convert to tf32)
        #pragma unroll
        for (int i = 0; i < 8; i++) {
            int lin = tid + i * 128;
            int r = lin >> 4, c4 = (lin & 15) << 2;
            float4 kv = *(const float4*)(Kg + (size_t)(s0 + r) * HD_ + c4);
            float4 vv = *(const float4*)(Vg + (size_t)(s0 + r) * HD_ + c4);
            KP[r][c4 + 0] = __uint_as_float(f2tf32(kv.x));
            KP[r][c4 + 1] = __uint_as_float(f2tf32(kv.y));
            KP[r][c4 + 2] = __uint_as_float(f2tf32(kv.z));
            KP[r][c4 + 3] = __uint_as_float(f2tf32(kv.w));
            Vs[r][c4 + 0] = __uint_as_float(f2tf32(vv.x));
            Vs[r][c4 + 1] = __uint_as_float(f2tf32(vv.y));
            Vs[r][c4 + 2] = __uint_as_float(f2tf32(vv.z));
            Vs[r][c4 + 3] = __uint_as_float(f2tf32(vv.w));
        }
        __syncthreads();

        // ---- S = (Q*scale) @ K^T  (64x64 per block, 16x64 per warp)
        float sacc[8][4];
        #pragma unroll
        for (int i = 0; i < 8; i++)
            #pragma unroll
            for (int e = 0; e < 4; e++) sacc[i][e] = 0.0f;
        #pragma unroll
        for (int k8 = 0; k8 < 8; k8++) {
            #pragma unroll
            for (int nt = 0; nt < 8; nt++) {
                uint32_t b0 = __float_as_uint(KP[nt * 8 + g][k8 * 8 + tig]);
                uint32_t b1 = __float_as_uint(KP[nt * 8 + g][k8 * 8 + tig + 4]);
                mma_tf32(sacc[nt], qf[k8][0], qf[k8][1], qf[k8][2], qf[k8][3], b0, b1);
            }
        }
        __syncthreads();   // everyone done reading K before P overwrites KP

        // ---- online softmax (rows g and g+8 of this warp's 16-row tile)
        float mx0 = -1e30f, mx1 = -1e30f;
        #pragma unroll
        for (int nt = 0; nt < 8; nt++) {
            mx0 = fmaxf(mx0, fmaxf(sacc[nt][0], sacc[nt][1]));
            mx1 = fmaxf(mx1, fmaxf(sacc[nt][2], sacc[nt][3]));
        }
        mx0 = fmaxf(mx0, __shfl_xor_sync(0xffffffffu, mx0, 1));
        mx0 = fmaxf(mx0, __shfl_xor_sync(0xffffffffu, mx0, 2));
        mx1 = fmaxf(mx1, __shfl_xor_sync(0xffffffffu, mx1, 1));
        mx1 = fmaxf(mx1, __shfl_xor_sync(0xffffffffu, mx1, 2));
        float nm0 = fmaxf(m0r, mx0), nm1 = fmaxf(m1r, mx1);
        float cr0 = __expf(m0r - nm0), cr1 = __expf(m1r - nm1);
        m0r = nm0; m1r = nm1;

        float p[8][4];
        float sum0 = 0.0f, sum1 = 0.0f;
        #pragma unroll
        for (int nt = 0; nt < 8; nt++) {
            p[nt][0] = __expf(sacc[nt][0] - nm0);
            p[nt][1] = __expf(sacc[nt][1] - nm0);
            p[nt][2] = __expf(sacc[nt][2] - nm1);
            p[nt][3] = __expf(sacc[nt][3] - nm1);
            sum0 += p[nt][0] + p[nt][1];
            sum1 += p[nt][2] + p[nt][3];
        }
        sum0 += __shfl_xor_sync(0xffffffffu, sum0, 1);
        sum0 += __shfl_xor_sync(0xffffffffu, sum0, 2);
        sum1 += __shfl_xor_sync(0xffffffffu, sum1, 1);
        sum1 += __shfl_xor_sync(0xffffffffu, sum1, 2);
        l0r = l0r * cr0 + sum0;
        l1r = l1r * cr1 + sum1;
        #pragma unroll
        for (int nt = 0; nt < 8; nt++) {
            of[nt][0] *= cr0; of[nt][1] *= cr0;
            of[nt][2] *= cr1; of[nt][3] *= cr1;
        }

        // ---- store P (tf32) into this warp's own rows of KP
        #pragma unroll
        for (int nt = 0; nt < 8; nt++) {
            float2 v01, v23;
            v01.x = __uint_as_float(f2tf32(p[nt][0]));
            v01.y = __uint_as_float(f2tf32(p[nt][1]));
            v23.x = __uint_as_float(f2tf32(p[nt][2]));
            v23.y = __uint_as_float(f2tf32(p[nt][3]));
            *(float2*)&KP[wrow + g    ][nt * 8 + tig * 2] = v01;
            *(float2*)&KP[wrow + g + 8][nt * 8 + tig * 2] = v23;
        }
        __syncwarp();

        // ---- O += P @ V
        #pragma unroll
        for (int k8 = 0; k8 < 8; k8++) {
            uint32_t a0 = __float_as_uint(KP[wrow + g    ][k8 * 8 + tig]);
            uint32_t a1 = __float_as_uint(KP[wrow + g + 8][k8 * 8 + tig]);
            uint32_t a2 = __float_as_uint(KP[wrow + g    ][k8 * 8 + tig + 4]);
            uint32_t a3 = __float_as_uint(KP[wrow + g + 8][k8 * 8 + tig + 4]);
            #pragma unroll
            for (int nt = 0; nt < 8; nt++) {
                uint32_t b0 = __float_as_uint(Vs[k8 * 8 + tig    ][nt * 8 + g]);
                uint32_t b1 = __float_as_uint(Vs[k8 * 8 + tig + 4][nt * 8 + g]);
                mma_tf32(of[nt], a0, a1, a2, a3, b0, b1);
            }
        }
    }

    // ---- epilogue: normalize and write [b, t, n, h]
    const float inv0 = 1.0f / l0r;
    const float inv1 = 1.0f / l1r;
    const int t0 = q0 + wrow + g;
    #pragma unroll
    for (int nt = 0; nt < 8; nt++) {
        const int h = nt * 8 + tig * 2;
        float2 v01, v23;
        v01.x = of[nt][0] * inv0; v01.y = of[nt][1] * inv0;
        v23.x = of[nt][2] * inv1; v23.y = of[nt][3] * inv1;
        *(float2*)(O + (((size_t)b * T_ + t0    ) * NH_ + n) * HD_ + h) = v01;
        *(float2*)(O + (((size_t)b * T_ + t0 + 8) * NH_ + n) * HD_ + h) = v23;
    }
}

// ---------------------------------------------------------------------------
// Launch
// Inputs: 0:q 1:v 2:k 3:w_query 4:b_query 5:w_value 6:b_value 7:w_key 8:b_key
//         9:w_projection 10:b_projection
// ---------------------------------------------------------------------------
extern "C" void kernel_launch(void* const* d_in, const int* in_sizes, int n_in,
                              void* d_out, int out_size)
{
    const float* q_in = (const float*)d_in[0];
    const float* v_in = (const float*)d_in[1];
    const float* k_in = (const float*)d_in[2];
    const float* w_q  = (const float*)d_in[3];
    const float* b_q  = (const float*)d_in[4];
    const float* w_v  = (const float*)d_in[5];
    const float* b_v  = (const float*)d_in[6];
    const float* w_k  = (const float*)d_in[7];
    const float* b_k  = (const float*)d_in[8];
    const float* w_p  = (const float*)d_in[9];
    const float* b_p  = (const float*)d_in[10];
    float* out = (float*)d_out;

    float *gq, *gk, *gv, *gattn, *gwpt;
    cudaGetSymbolAddress((void**)&gq,    g_q);
    cudaGetSymbolAddress((void**)&gk,    g_k);
    cudaGetSymbolAddress((void**)&gv,    g_v);
    cudaGetSymbolAddress((void**)&gattn, g_attn);
    cudaGetSymbolAddress((void**)&gwpt,  g_wpt);

    // 1. transpose w_projection
    transpose_wp_kernel<<<(NDH_ * D_ + 255) / 256, 256>>>(w_p, gwpt);

    // 2-4. QKV projections (bf16-split tensor core)
    dim3 ggrid(NDH_ / 128, BT_ / 128);   // (8, 32)
    gemm_bf16x2_kernel<0><<<ggrid, 256>>>(q_in, w_q, b_q, gq, BT_, D_, NDH_);
    gemm_bf16x2_kernel<0><<<ggrid, 256>>>(k_in, w_k, b_k, gk, BT_, D_, NDH_);
    gemm_bf16x2_kernel<0><<<ggrid, 256>>>(v_in, w_v, b_v, gv, BT_, D_, NDH_);

    // 5. attention (tf32 tensor core flash attention)
    dim3 agrid(T_ / 64, B_ * NH_);       // (32, 32)
    attn_tc_kernel<<<agrid, 128>>>(gq, gk, gv, gattn);

    // 6. output projection
    dim3 pgrid(D_ / 128, BT_ / 128);     // (8, 32)
    gemm_bf16x2_kernel<1><<<pgrid, 256>>>(gattn, gwpt, b_p, out, BT_, NDH_, D_);
}

// round 4
// speedup vs baseline: 1.0005x; 1.0005x over previous
#include <cuda_runtime.h>
#include <cuda_bf16.h>
#include <math.h>
#include <stdint.h>

#define B_   2
#define T_   2048
#define D_   1024
#define NH_  16
#define HD_  64
#define BT_  (B_*T_)      // 4096
#define NDH_ (NH_*HD_)    // 1024

// Scratch (allocation-free: __device__ globals)
__device__ float g_q[(size_t)B_*NH_*T_*HD_];     // [b,n,t,h]
__device__ float g_k[(size_t)B_*NH_*T_*HD_];     // [b,n,t,h]
__device__ float g_v[(size_t)B_*NH_*T_*HD_];     // [b,n,t,h]
__device__ float g_attn[(size_t)BT_*NDH_];       // [b,t,n,h] == [4096, 1024]
__device__ float g_wpt[(size_t)NDH_*D_];         // [(n,h), d]

// ---------------------------------------------------------------------------
// helpers
// ---------------------------------------------------------------------------
__device__ __forceinline__ uint32_t f2tf32(float x) {
    uint32_t r;
    asm("cvt.rna.tf32.f32 %0, %1;" : "=r"(r) : "f"(x));
    return r;
}

__device__ __forceinline__ void mma_tf32(float* c,
                                         uint32_t a0, uint32_t a1, uint32_t a2, uint32_t a3,
                                         uint32_t b0, uint32_t b1) {
    asm volatile("mma.sync.aligned.m16n8k8.row.col.f32.tf32.tf32.f32 "
                 "{%0,%1,%2,%3}, {%4,%5,%6,%7}, {%8,%9}, {%0,%1,%2,%3};"
                 : "+f"(c[0]), "+f"(c[1]), "+f"(c[2]), "+f"(c[3])
                 : "r"(a0), "r"(a1), "r"(a2), "r"(a3), "r"(b0), "r"(b1));
}

__device__ __forceinline__ void mma_bf16(float* c,
                                         uint32_t a0, uint32_t a1, uint32_t a2, uint32_t a3,
                                         uint32_t b0, uint32_t b1) {
    asm volatile("mma.sync.aligned.m16n8k16.row.col.f32.bf16.bf16.f32 "
                 "{%0,%1,%2,%3}, {%4,%5,%6,%7}, {%8,%9}, {%0,%1,%2,%3};"
                 : "+f"(c[0]), "+f"(c[1]), "+f"(c[2]), "+f"(c[3])
                 : "r"(a0), "r"(a1), "r"(a2), "r"(a3), "r"(b0), "r"(b1));
}

// split two fp32 (even,odd along k) into packed bf16x2 hi and lo parts
__device__ __forceinline__ void split2(float e, float o, uint32_t& hi, uint32_t& lo) {
    __nv_bfloat162 h = __floats2bfloat162_rn(e, o);
    float he = __low2float(h), ho = __high2float(h);
    __nv_bfloat162 l = __floats2bfloat162_rn(e - he, o - ho);
    hi = *reinterpret_cast<uint32_t*>(&h);
    lo = *reinterpret_cast<uint32_t*>(&l);
}

// ---------------------------------------------------------------------------
// Transpose w_projection [N, D, H] -> [(n,h), d]
// ---------------------------------------------------------------------------
__global__ void transpose_wp_kernel(const float* __restrict__ wp,
                                    float* __restrict__ wpt)
{
    int idx = blockIdx.x * blockDim.x + threadIdx.x;
    if (idx >= NDH_ * D_) return;
    int d = idx % D_;
    int k = idx / D_;          // k = n*H + h
    int n = k / HD_;
    int h = k % HD_;
    wpt[idx] = wp[((size_t)n * D_ + d) * HD_ + h];
}

// ---------------------------------------------------------------------------
// bf16-split tensor-core GEMM: C = A[M,K] * B[K,N] + bias, near-fp32 accuracy.
// 128x128 block tile, BK=16, 256 threads = 8 warps (4 M x 2 N), warp 32x64.
// MODE 0: C -> [B, N, T, H];  MODE 1: C -> [M, Ncols] row-major.
// ---------------------------------------------------------------------------
template<int MODE>
__global__ __launch_bounds__(256)
void gemm_bf16x2_kernel(const float* __restrict__ A,
                        const float* __restrict__ Bm,
                        const float* __restrict__ bias,
                        float* __restrict__ C,
                        int M, int K, int Ncols)
{
    __shared__ uint32_t AsHi[8][136];
    __shared__ uint32_t AsLo[8][136];
    __shared__ uint32_t BsHi[8][136];
    __shared__ uint32_t BsLo[8][136];

    const int tid  = threadIdx.x;
    const int warp = tid >> 5;
    const int lane = tid & 31;
    const int g    = lane >> 2;
    const int tig  = lane & 3;
    const int wm   = warp >> 1;   // 0..3
    const int wn   = warp & 1;    // 0..1
    const int m0   = blockIdx.y * 128;
    const int n0   = blockIdx.x * 128;

    const int la_m    = tid >> 1;        // 0..127
    const int la_half = tid & 1;         // k-half: 0 or 1 (8 floats each)
    const int lb_pr   = tid >> 5;        // 0..7 (pair-row)
    const int lb_n4   = (tid & 31) << 2; // 0..124

    float acc[2][8][4];
    #pragma unroll
    for (int i = 0; i < 2; i++)
        #pragma unroll
        for (int j = 0; j < 8; j++)
            #pragma unroll
            for (int e = 0; e < 4; e++)
                acc[i][j][e] = 0.0f;

    for (int k0 = 0; k0 < K; k0 += 16) {
        __syncthreads();
        // ---- load A tile: rows m0..m0+127, k0..k0+15, packed pairs along k
        {
            const float4* ap = (const float4*)(A + (size_t)(m0 + la_m) * K + k0 + la_half * 8);
            float4 r0 = ap[0];
            float4 r1 = ap[1];
            uint32_t h, l;
            const int pr = la_half * 4;
            split2(r0.x, r0.y, h, l); AsHi[pr + 0][la_m] = h; AsLo[pr + 0][la_m] = l;
            split2(r0.z, r0.w, h, l); AsHi[pr + 1][la_m] = h; AsLo[pr + 1][la_m] = l;
            split2(r1.x, r1.y, h, l); AsHi[pr + 2][la_m] = h; AsLo[pr + 2][la_m] = l;
            split2(r1.z, r1.w, h, l); AsHi[pr + 3][la_m] = h; AsLo[pr + 3][la_m] = l;
        }
        // ---- load B tile: rows k0..k0+15, cols n0..n0+127
        {
            const float* bp = Bm + (size_t)(k0 + 2 * lb_pr) * Ncols + n0 + lb_n4;
            float4 r0 = *(const float4*)bp;
            float4 r1 = *(const float4*)(bp + Ncols);
            uint32_t h0, l0, h1, l1, h2, l2, h3, l3;
            split2(r0.x, r1.x, h0, l0);
            split2(r0.y, r1.y, h1, l1);
            split2(r0.z, r1.z, h2, l2);
            split2(r0.w, r1.w, h3, l3);
            *(uint4*)&BsHi[lb_pr][lb_n4] = make_uint4(h0, h1, h2, h3);
            *(uint4*)&BsLo[lb_pr][lb_n4] = make_uint4(l0, l1, l2, l3);
        }
        __syncthreads();

        // ---- fragments + mma
        uint32_t bh[8][2], bl[8][2];
        #pragma unroll
        for (int nt = 0; nt < 8; nt++) {
            const int col = wn * 64 + nt * 8 + g;
            bh[nt][0] = BsHi[tig][col];     bh[nt][1] = BsHi[tig + 4][col];
            bl[nt][0] = BsLo[tig][col];     bl[nt][1] = BsLo[tig + 4][col];
        }
        #pragma unroll
        for (int mt = 0; mt < 2; mt++) {
            const int rb = wm * 32 + mt * 16;
            uint32_t ah0 = AsHi[tig][rb + g],     ah1 = AsHi[tig][rb + g + 8];
            uint32_t ah2 = AsHi[tig + 4][rb + g], ah3 = AsHi[tig + 4][rb + g + 8];
            uint32_t al0 = AsLo[tig][rb + g],     al1 = AsLo[tig][rb + g + 8];
            uint32_t al2 = AsLo[tig + 4][rb + g], al3 = AsLo[tig + 4][rb + g + 8];
            #pragma unroll
            for (int nt = 0; nt < 8; nt++) {
                mma_bf16(acc[mt][nt], ah0, ah1, ah2, ah3, bh[nt][0], bh[nt][1]);
                mma_bf16(acc[mt][nt], ah0, ah1, ah2, ah3, bl[nt][0], bl[nt][1]);
                mma_bf16(acc[mt][nt], al0, al1, al2, al3, bh[nt][0], bh[nt][1]);
            }
        }
    }

    // ---- epilogue
    #pragma unroll
    for (int mt = 0; mt < 2; mt++) {
        #pragma unroll
        for (int nt = 0; nt < 8; nt++) {
            const int cbase = n0 + wn * 64 + nt * 8 + tig * 2;
            #pragma unroll
            for (int e = 0; e < 4; e++) {
                const int m  = m0 + wm * 32 + mt * 16 + g + ((e >= 2) ? 8 : 0);
                const int cc = cbase + (e & 1);
                float val = acc[mt][nt][e] + bias[cc];
                if (MODE == 0) {
                    int b = m / T_, t = m % T_;
                    int n = cc >> 6, h = cc & 63;
                    C[(((size_t)b * NH_ + n) * T_ + t) * HD_ + h] = val;
                } else {
                    C[(size_t)m * Ncols + cc] = val;
                }
            }
        }
    }
}

// ---------------------------------------------------------------------------
// tf32 tensor-core flash attention.
// Block = 128 threads (4 warps), handles 64 query rows of one (b, head).
// Each warp owns 16 rows. KV tiles of 64 keys; K buffer is reused for P.
// Output written to [b, t, n, h].
// ---------------------------------------------------------------------------
__global__ __launch_bounds__(128)
void attn_tc_kernel(const float* __restrict__ Q,
                    const float* __restrict__ K,
                    const float* __restrict__ V,
                    float* __restrict__ O)
{
    __shared__ float KP[64][68];   // K tile (tf32 bits), reused for P
    __shared__ float Vs[64][72];   // V tile (tf32 bits)

    const int tid  = threadIdx.x;
    const int warp = tid >> 5;
    const int lane = tid & 31;
    const int g    = lane >> 2;
    const int tig  = lane & 3;
    const int bn   = blockIdx.y;        // b*NH + n
    const int b    = bn / NH_;
    const int n    = bn % NH_;
    const int q0   = blockIdx.x * 64;
    const int wrow = warp * 16;

    const float* Qg = Q + ((size_t)bn * T_ + q0) * HD_;
    const float* Kg = K + (size_t)bn * T_ * HD_;
    const float* Vg = V + (size_t)bn * T_ * HD_;

    // ---- stage Q tile into KP, then load persistent A-fragments (prescaled)
    #pragma unroll
    for (int i = 0; i < 8; i++) {
        int lin = tid + i * 128;          // float4 slots over 64x16
        int r = lin >> 4, c4 = (lin & 15) << 2;
        float4 v4 = *(const float4*)(Qg + r * HD_ + c4);
        KP[r][c4 + 0] = v4.x; KP[r][c4 + 1] = v4.y;
        KP[r][c4 + 2] = v4.z; KP[r][c4 + 3] = v4.w;
    }
    __syncthreads();
    uint32_t qf[8][4];
    const float qscale = 0.125f;          // 1/sqrt(64)
    #pragma unroll
    for (int k8 = 0; k8 < 8; k8++) {
        qf[k8][0] = f2tf32(KP[wrow + g    ][k8 * 8 + tig    ] * qscale);
        qf[k8][1] = f2tf32(KP[wrow + g + 8][k8 * 8 + tig    ] * qscale);
        qf[k8][2] = f2tf32(KP[wrow + g    ][k8 * 8 + tig + 4] * qscale);
        qf[k8][3] = f2tf32(KP[wrow + g + 8][k8 * 8 + tig + 4] * qscale);
    }

    float of[8][4];
    #pragma unroll
    for (int i = 0; i < 8; i++)
        #pragma unroll
        for (int e = 0; e < 4; e++) of[i][e] = 0.0f;
    float m0r = -1e30f, m1r = -1e30f;
    float l0r = 0.0f,   l1r = 0.0f;

    for (int s0 = 0; s0 < T_; s0 += 64) {
        __syncthreads();   // previous tile's P/V reads complete
        // ---- load K -> KP, V -> Vs (convert to tf32)
        #pragma unroll
        for (int i = 0; i < 8; i++) {
            int lin = tid + i * 128;
            int r = lin >> 4, c4 = (lin & 15) << 2;
            float4 kv = *(const float4*)(Kg + (size_t)(s0 + r) * HD_ + c4);
            float4 vv = *(const float4*)(Vg + (size_t)(s0 + r) * HD_ + c4);
            KP[r][c4 + 0] = __uint_as_float(f2tf32(kv.x));
            KP[r][c4 + 1] = __uint_as_float(f2tf32(kv.y));
            KP[r][c4 + 2] = __uint_as_float(f2tf32(kv.z));
            KP[r][c4 + 3] = __uint_as_float(f2tf32(kv.w));
            Vs[r][c4 + 0] = __uint_as_float(f2tf32(vv.x));
            Vs[r][c4 + 1] = __uint_as_float(f2tf32(vv.y));
            Vs[r][c4 + 2] = __uint_as_float(f2tf32(vv.z));
            Vs[r][c4 + 3] = __uint_as_float(f2tf32(vv.w));
        }
        __syncthreads();

        // ---- S = (Q*scale) @ K^T  (64x64 per block, 16x64 per warp)
        float sacc[8][4];
        #pragma unroll
        for (int i = 0; i < 8; i++)
            #pragma unroll
            for (int e = 0; e < 4; e++) sacc[i][e] = 0.0f;
        #pragma unroll
        for (int k8 = 0; k8 < 8; k8++) {
            #pragma unroll
            for (int nt = 0; nt < 8; nt++) {
                uint32_t b0 = __float_as_uint(KP[nt * 8 + g][k8 * 8 + tig]);
                uint32_t b1 = __float_as_uint(KP[nt * 8 + g][k8 * 8 + tig + 4]);
                mma_tf32(sacc[nt], qf[k8][0], qf[k8][1], qf[k8][2], qf[k8][3], b0, b1);
            }
        }
        __syncthreads();   // everyone done reading K before P overwrites KP

        // ---- online softmax (rows g and g+8 of this warp's 16-row tile)
        float mx0 = -1e30f, mx1 = -1e30f;
        #pragma unroll
        for (int nt = 0; nt < 8; nt++) {
            mx0 = fmaxf(mx0, fmaxf(sacc[nt][0], sacc[nt][1]));
            mx1 = fmaxf(mx1, fmaxf(sacc[nt][2], sacc[nt][3]));
        }
        mx0 = fmaxf(mx0, __shfl_xor_sync(0xffffffffu, mx0, 1));
        mx0 = fmaxf(mx0, __shfl_xor_sync(0xffffffffu, mx0, 2));
        mx1 = fmaxf(mx1, __shfl_xor_sync(0xffffffffu, mx1, 1));
        mx1 = fmaxf(mx1, __shfl_xor_sync(0xffffffffu, mx1, 2));
        float nm0 = fmaxf(m0r, mx0), nm1 = fmaxf(m1r, mx1);
        float cr0 = __expf(m0r - nm0), cr1 = __expf(m1r - nm1);
        m0r = nm0; m1r = nm1;

        float p[8][4];
        float sum0 = 0.0f, sum1 = 0.0f;
        #pragma unroll
        for (int nt = 0; nt < 8; nt++) {
            p[nt][0] = __expf(sacc[nt][0] - nm0);
            p[nt][1] = __expf(sacc[nt][1] - nm0);
            p[nt][2] = __expf(sacc[nt][2] - nm1);
            p[nt][3] = __expf(sacc[nt][3] - nm1);
            sum0 += p[nt][0] + p[nt][1];
            sum1 += p[nt][2] + p[nt][3];
        }
        sum0 += __shfl_xor_sync(0xffffffffu, sum0, 1);
        sum0 += __shfl_xor_sync(0xffffffffu, sum0, 2);
        sum1 += __shfl_xor_sync(0xffffffffu, sum1, 1);
        sum1 += __shfl_xor_sync(0xffffffffu, sum1, 2);
        l0r = l0r * cr0 + sum0;
        l1r = l1r * cr1 + sum1;
        #pragma unroll
        for (int nt = 0; nt < 8; nt++) {
            of[nt][0] *= cr0; of[nt][1] *= cr0;
            of[nt][2] *= cr1; of[nt][3] *= cr1;
        }

        // ---- store P (tf32) into this warp's own rows of KP
        #pragma unroll
        for (int nt = 0; nt < 8; nt++) {
            float2 v01, v23;
            v01.x = __uint_as_float(f2tf32(p[nt][0]));
            v01.y = __uint_as_float(f2tf32(p[nt][1]));
            v23.x = __uint_as_float(f2tf32(p[nt][2]));
            v23.y = __uint_as_float(f2tf32(p[nt][3]));
            *(float2*)&KP[wrow + g    ][nt * 8 + tig * 2] = v01;
            *(float2*)&KP[wrow + g + 8][nt * 8 + tig * 2] = v23;
        }
        __syncwarp();

        // ---- O += P @ V
        #pragma unroll
        for (int k8 = 0; k8 < 8; k8++) {
            uint32_t a0 = __float_as_uint(KP[wrow + g    ][k8 * 8 + tig]);
            uint32_t a1 = __float_as_uint(KP[wrow + g + 8][k8 * 8 + tig]);
            uint32_t a2 = __float_as_uint(KP[wrow + g    ][k8 * 8 + tig + 4]);
            uint32_t a3 = __float_as_uint(KP[wrow + g + 8][k8 * 8 + tig + 4]);
            #pragma unroll
            for (int nt = 0; nt < 8; nt++) {
                uint32_t b0 = __float_as_uint(Vs[k8 * 8 + tig    ][nt * 8 + g]);
                uint32_t b1 = __float_as_uint(Vs[k8 * 8 + tig + 4][nt * 8 + g]);
                mma_tf32(of[nt], a0, a1, a2, a3, b0, b1);
            }
        }
    }

    // ---- epilogue: normalize and write [b, t, n, h]
    const float inv0 = 1.0f / l0r;
    const float inv1 = 1.0f / l1r;
    const int t0 = q0 + wrow + g;
    #pragma unroll
    for (int nt = 0; nt < 8; nt++) {
        const int h = nt * 8 + tig * 2;
        float2 v01, v23;
        v01.x = of[nt][0] * inv0; v01.y = of[nt][1] * inv0;
        v23.x = of[nt][2] * inv1; v23.y = of[nt][3] * inv1;
        *(float2*)(O + (((size_t)b * T_ + t0    ) * NH_ + n) * HD_ + h) = v01;
        *(float2*)(O + (((size_t)b * T_ + t0 + 8) * NH_ + n) * HD_ + h) = v23;
    }
}

// ---------------------------------------------------------------------------
// Launch
// Inputs: 0:q 1:v 2:k 3:w_query 4:b_query 5:w_value 6:b_value 7:w_key 8:b_key
//         9:w_projection 10:b_projection
// ---------------------------------------------------------------------------
extern "C" void kernel_launch(void* const* d_in, const int* in_sizes, int n_in,
                              void* d_out, int out_size)
{
    const float* q_in = (const float*)d_in[0];
    const float* v_in = (const float*)d_in[1];
    const float* k_in = (const float*)d_in[2];
    const float* w_q  = (const float*)d_in[3];
    const float* b_q  = (const float*)d_in[4];
    const float* w_v  = (const float*)d_in[5];
    const float* b_v  = (const float*)d_in[6];
    const float* w_k  = (const float*)d_in[7];
    const float* b_k  = (const float*)d_in[8];
    const float* w_p  = (const float*)d_in[9];
    const float* b_p  = (const float*)d_in[10];
    float* out = (float*)d_out;

    float *gq, *gk, *gv, *gattn, *gwpt;
    cudaGetSymbolAddress((void**)&gq,    g_q);
    cudaGetSymbolAddress((void**)&gk,    g_k);
    cudaGetSymbolAddress((void**)&gv,    g_v);
    cudaGetSymbolAddress((void**)&gattn, g_attn);
    cudaGetSymbolAddress((void**)&gwpt,  g_wpt);

    // 1. transpose w_projection
    transpose_wp_kernel<<<(NDH_ * D_ + 255) / 256, 256>>>(w_p, gwpt);

    // 2-4. QKV projections (bf16-split tensor core)
    dim3 ggrid(NDH_ / 128, BT_ / 128);   // (8, 32)
    gemm_bf16x2_kernel<0><<<ggrid, 256>>>(q_in, w_q, b_q, gq, BT_, D_, NDH_);
    gemm_bf16x2_kernel<0><<<ggrid, 256>>>(k_in, w_k, b_k, gk, BT_, D_, NDH_);
    gemm_bf16x2_kernel<0><<<ggrid, 256>>>(v_in, w_v, b_v, gv, BT_, D_, NDH_);

    // 5. attention (tf32 tensor core flash attention)
    dim3 agrid(T_ / 64, B_ * NH_);       // (32, 32)
    attn_tc_kernel<<<agrid, 128>>>(gq, gk, gv, gattn);

    // 6. output projection
    dim3 pgrid(D_ / 128, BT_ / 128);     // (8, 32)
    gemm_bf16x2_kernel<1><<<pgrid, 256>>>(gattn, gwpt, b_p, out, BT_, NDH_, D_);
}

// round 5
// speedup vs baseline: 1.0241x; 1.0236x over previous
#include <cuda_runtime.h>
#include <cuda_bf16.h>
#include <math.h>
#include <stdint.h>

#define B_   2
#define T_   2048
#define D_   1024
#define NH_  16
#define HD_  64
#define BT_  (B_*T_)      // 4096
#define NDH_ (NH_*HD_)    // 1024

// Scratch (allocation-free: __device__ globals)
__device__ float g_q[(size_t)B_*NH_*T_*HD_];     // [b,n,t,h]
__device__ float g_k[(size_t)B_*NH_*T_*HD_];     // [b,n,t,h]
__device__ float g_v[(size_t)B_*NH_*T_*HD_];     // [b,n,t,h]
__device__ float g_attn[(size_t)BT_*NDH_];       // [b,t,n,h]
__device__ float g_wpt[(size_t)NDH_*D_];         // [(n,h), d]

// ---------------------------------------------------------------------------
// helpers
// ---------------------------------------------------------------------------
__device__ __forceinline__ uint32_t f2tf32(float x) {
    uint32_t r;
    asm("cvt.rna.tf32.f32 %0, %1;" : "=r"(r) : "f"(x));
    return r;
}

__device__ __forceinline__ float ex2(float x) {
    float r;
    asm("ex2.approx.f32 %0, %1;" : "=f"(r) : "f"(x));
    return r;
}

__device__ __forceinline__ void mma_tf32(float* c,
                                         uint32_t a0, uint32_t a1, uint32_t a2, uint32_t a3,
                                         uint32_t b0, uint32_t b1) {
    asm volatile("mma.sync.aligned.m16n8k8.row.col.f32.tf32.tf32.f32 "
                 "{%0,%1,%2,%3}, {%4,%5,%6,%7}, {%8,%9}, {%0,%1,%2,%3};"
                 : "+f"(c[0]), "+f"(c[1]), "+f"(c[2]), "+f"(c[3])
                 : "r"(a0), "r"(a1), "r"(a2), "r"(a3), "r"(b0), "r"(b1));
}

__device__ __forceinline__ void mma_bf16(float* c,
                                         uint32_t a0, uint32_t a1, uint32_t a2, uint32_t a3,
                                         uint32_t b0, uint32_t b1) {
    asm volatile("mma.sync.aligned.m16n8k16.row.col.f32.bf16.bf16.f32 "
                 "{%0,%1,%2,%3}, {%4,%5,%6,%7}, {%8,%9}, {%0,%1,%2,%3};"
                 : "+f"(c[0]), "+f"(c[1]), "+f"(c[2]), "+f"(c[3])
                 : "r"(a0), "r"(a1), "r"(a2), "r"(a3), "r"(b0), "r"(b1));
}

// split two fp32 (even,odd along k) into packed bf16x2 hi and lo parts
__device__ __forceinline__ void split2(float e, float o, uint32_t& hi, uint32_t& lo) {
    __nv_bfloat162 h = __floats2bfloat162_rn(e, o);
    float he = __low2float(h), ho = __high2float(h);
    __nv_bfloat162 l = __floats2bfloat162_rn(e - he, o - ho);
    hi = *reinterpret_cast<uint32_t*>(&h);
    lo = *reinterpret_cast<uint32_t*>(&l);
}

// ---------------------------------------------------------------------------
// Transpose w_projection [N, D, H] -> [(n,h), d]
// ---------------------------------------------------------------------------
__global__ void transpose_wp_kernel(const float* __restrict__ wp,
                                    float* __restrict__ wpt)
{
    int idx = blockIdx.x * blockDim.x + threadIdx.x;
    if (idx >= NDH_ * D_) return;
    int d = idx % D_;
    int k = idx / D_;
    int n = k / HD_;
    int h = k % HD_;
    wpt[idx] = wp[((size_t)n * D_ + d) * HD_ + h];
}

// ---------------------------------------------------------------------------
// bf16-split tensor-core GEMM, double-buffered smem, 1 sync per k-tile.
// 128x128 block tile, BK=16, 8 warps (2 M x 4 N), warp tile 64x32.
// MODE 0: C -> [B, N, T, H];  MODE 1: C -> [M, Ncols] row-major.
// ---------------------------------------------------------------------------
template<int MODE>
__global__ __launch_bounds__(256)
void gemm_bf16x2_kernel(const float* __restrict__ A,
                        const float* __restrict__ Bm,
                        const float* __restrict__ bias,
                        float* __restrict__ C,
                        int M, int K, int Ncols)
{
    __shared__ uint32_t AsHi[2][8][136];
    __shared__ uint32_t AsLo[2][8][136];
    __shared__ uint32_t BsHi[2][8][136];
    __shared__ uint32_t BsLo[2][8][136];

    const int tid  = threadIdx.x;
    const int warp = tid >> 5;
    const int lane = tid & 31;
    const int g    = lane >> 2;
    const int tig  = lane & 3;
    const int wm   = warp >> 2;   // 0..1  (64 rows each)
    const int wn   = warp & 3;    // 0..3  (32 cols each)
    const int m0   = blockIdx.y * 128;
    const int n0   = blockIdx.x * 128;

    const int la_m    = tid >> 1;        // 0..127
    const int la_half = tid & 1;         // k-half: 0 or 1 (8 floats each)
    const int lb_pr   = tid >> 5;        // 0..7 (pair-row)
    const int lb_n4   = (tid & 31) << 2; // 0..124

    float acc[4][4][4];
    #pragma unroll
    for (int i = 0; i < 4; i++)
        #pragma unroll
        for (int j = 0; j < 4; j++)
            #pragma unroll
            for (int e = 0; e < 4; e++)
                acc[i][j][e] = 0.0f;

    float4 ar0, ar1, br0, br1;

    auto gload = [&](int k0) {
        const float4* a4 = (const float4*)(A + (size_t)(m0 + la_m) * K + k0 + la_half * 8);
        ar0 = a4[0];
        ar1 = a4[1];
        const float* bp = Bm + (size_t)(k0 + 2 * lb_pr) * Ncols + n0 + lb_n4;
        br0 = *(const float4*)bp;
        br1 = *(const float4*)(bp + Ncols);
    };

    auto sstore = [&](int st) {
        uint32_t h, l;
        const int pr = la_half * 4;
        split2(ar0.x, ar0.y, h, l); AsHi[st][pr + 0][la_m] = h; AsLo[st][pr + 0][la_m] = l;
        split2(ar0.z, ar0.w, h, l); AsHi[st][pr + 1][la_m] = h; AsLo[st][pr + 1][la_m] = l;
        split2(ar1.x, ar1.y, h, l); AsHi[st][pr + 2][la_m] = h; AsLo[st][pr + 2][la_m] = l;
        split2(ar1.z, ar1.w, h, l); AsHi[st][pr + 3][la_m] = h; AsLo[st][pr + 3][la_m] = l;
        uint32_t h0, l0, h1, l1, h2, l2, h3, l3;
        split2(br0.x, br1.x, h0, l0);
        split2(br0.y, br1.y, h1, l1);
        split2(br0.z, br1.z, h2, l2);
        split2(br0.w, br1.w, h3, l3);
        *(uint4*)&BsHi[st][lb_pr][lb_n4] = make_uint4(h0, h1, h2, h3);
        *(uint4*)&BsLo[st][lb_pr][lb_n4] = make_uint4(l0, l1, l2, l3);
    };

    auto compute = [&](int st) {
        uint32_t bh[4][2], bl[4][2];
        #pragma unroll
        for (int nt = 0; nt < 4; nt++) {
            const int col = wn * 32 + nt * 8 + g;
            bh[nt][0] = BsHi[st][tig][col];     bh[nt][1] = BsHi[st][tig + 4][col];
            bl[nt][0] = BsLo[st][tig][col];     bl[nt][1] = BsLo[st][tig + 4][col];
        }
        #pragma unroll
        for (int mt = 0; mt < 4; mt++) {
            const int rb = wm * 64 + mt * 16;
            uint32_t ah0 = AsHi[st][tig][rb + g],     ah1 = AsHi[st][tig][rb + g + 8];
            uint32_t ah2 = AsHi[st][tig + 4][rb + g], ah3 = AsHi[st][tig + 4][rb + g + 8];
            uint32_t al0 = AsLo[st][tig][rb + g],     al1 = AsLo[st][tig][rb + g + 8];
            uint32_t al2 = AsLo[st][tig + 4][rb + g], al3 = AsLo[st][tig + 4][rb + g + 8];
            #pragma unroll
            for (int nt = 0; nt < 4; nt++) {
                mma_bf16(acc[mt][nt], ah0, ah1, ah2, ah3, bh[nt][0], bh[nt][1]);
                mma_bf16(acc[mt][nt], ah0, ah1, ah2, ah3, bl[nt][0], bl[nt][1]);
                mma_bf16(acc[mt][nt], al0, al1, al2, al3, bh[nt][0], bh[nt][1]);
            }
        }
    };

    // prologue
    gload(0);
    sstore(0);
    __syncthreads();

    int st = 0;
    for (int k0 = 16; k0 < K; k0 += 16) {
        gload(k0);          // prefetch next tile (LDGs fly during MMAs)
        compute(st);
        sstore(st ^ 1);
        __syncthreads();
        st ^= 1;
    }
    compute(st);

    // ---- epilogue
    #pragma unroll
    for (int mt = 0; mt < 4; mt++) {
        #pragma unroll
        for (int nt = 0; nt < 4; nt++) {
            const int cbase = n0 + wn * 32 + nt * 8 + tig * 2;
            #pragma unroll
            for (int e = 0; e < 4; e++) {
                const int m  = m0 + wm * 64 + mt * 16 + g + ((e >= 2) ? 8 : 0);
                const int cc = cbase + (e & 1);
                float val = acc[mt][nt][e] + bias[cc];
                if (MODE == 0) {
                    int b = m >> 11, t = m & (T_ - 1);
                    int n = cc >> 6, h = cc & 63;
                    C[(((size_t)b * NH_ + n) * T_ + t) * HD_ + h] = val;
                } else {
                    C[(size_t)m * Ncols + cc] = val;
                }
            }
        }
    }
}

// ---------------------------------------------------------------------------
// tf32 tensor-core flash attention (dedicated P buffer, exp2 softmax).
// Block = 128 threads (4 warps), 64 query rows of one (b, head); warp owns 16.
// Dynamic smem: K[64][68] + V[64][72] + P[64][68] = 53248 B -> 4 CTAs/SM.
// 2 syncthreads per 64-key tile. Output written to [b, t, n, h].
// ---------------------------------------------------------------------------
__global__ __launch_bounds__(128, 4)
void attn_tc_kernel(const float* __restrict__ Q,
                    const float* __restrict__ K,
                    const float* __restrict__ V,
                    float* __restrict__ O)
{
    extern __shared__ float smx[];
    float* Kt = smx;                 // [64][68] tf32 bits
    float* Vt = smx + 64 * 68;       // [64][72] tf32 bits
    float* Pw = Vt  + 64 * 72;       // [64][68] per-warp P (also Q staging)

    const int tid  = threadIdx.x;
    const int warp = tid >> 5;
    const int lane = tid & 31;
    const int g    = lane >> 2;
    const int tig  = lane & 3;
    const int bn   = blockIdx.y;        // b*NH + n
    const int b    = bn / NH_;
    const int n    = bn % NH_;
    const int q0   = blockIdx.x * 64;
    const int wrow = warp * 16;

    const float* Qg = Q + ((size_t)bn * T_ + q0) * HD_;
    const float* Kg = K + (size_t)bn * T_ * HD_;
    const float* Vg = V + (size_t)bn * T_ * HD_;

    // ---- stage Q tile into Pw, then load persistent A-fragments
    #pragma unroll
    for (int i = 0; i < 8; i++) {
        int lin = tid + i * 128;          // float4 slots over 64x16
        int r = lin >> 4, c4 = (lin & 15) << 2;
        float4 v4 = *(const float4*)(Qg + r * HD_ + c4);
        Pw[r * 68 + c4 + 0] = v4.x; Pw[r * 68 + c4 + 1] = v4.y;
        Pw[r * 68 + c4 + 2] = v4.z; Pw[r * 68 + c4 + 3] = v4.w;
    }
    __syncthreads();
    // scale folds 1/sqrt(H) and log2(e) so softmax uses raw ex2
    const float qs = 0.125f * 1.4426950408889634f;
    uint32_t qf[8][4];
    #pragma unroll
    for (int k8 = 0; k8 < 8; k8++) {
        qf[k8][0] = f2tf32(Pw[(wrow + g    ) * 68 + k8 * 8 + tig    ] * qs);
        qf[k8][1] = f2tf32(Pw[(wrow + g + 8) * 68 + k8 * 8 + tig    ] * qs);
        qf[k8][2] = f2tf32(Pw[(wrow + g    ) * 68 + k8 * 8 + tig + 4] * qs);
        qf[k8][3] = f2tf32(Pw[(wrow + g + 8) * 68 + k8 * 8 + tig + 4] * qs);
    }

    float of[8][4];
    #pragma unroll
    for (int i = 0; i < 8; i++)
        #pragma unroll
        for (int e = 0; e < 4; e++) of[i][e] = 0.0f;
    float m0r = -1e30f, m1r = -1e30f;
    float l0r = 0.0f,   l1r = 0.0f;

    for (int s0 = 0; s0 < T_; s0 += 64) {
        __syncthreads();   // all warps done reading Kt/Vt of previous tile
        // ---- load K -> Kt, V -> Vt (convert to tf32)
        #pragma unroll
        for (int i = 0; i < 8; i++) {
            int lin = tid + i * 128;
            int r = lin >> 4, c4 = (lin & 15) << 2;
            float4 kv = *(const float4*)(Kg + (size_t)(s0 + r) * HD_ + c4);
            float4 vv = *(const float4*)(Vg + (size_t)(s0 + r) * HD_ + c4);
            Kt[r * 68 + c4 + 0] = __uint_as_float(f2tf32(kv.x));
            Kt[r * 68 + c4 + 1] = __uint_as_float(f2tf32(kv.y));
            Kt[r * 68 + c4 + 2] = __uint_as_float(f2tf32(kv.z));
            Kt[r * 68 + c4 + 3] = __uint_as_float(f2tf32(kv.w));
            Vt[r * 72 + c4 + 0] = __uint_as_float(f2tf32(vv.x));
            Vt[r * 72 + c4 + 1] = __uint_as_float(f2tf32(vv.y));
            Vt[r * 72 + c4 + 2] = __uint_as_float(f2tf32(vv.z));
            Vt[r * 72 + c4 + 3] = __uint_as_float(f2tf32(vv.w));
        }
        __syncthreads();

        // ---- S = (Q*qs) @ K^T  (scores in log2 domain)
        float sacc[8][4];
        #pragma unroll
        for (int i = 0; i < 8; i++)
            #pragma unroll
            for (int e = 0; e < 4; e++) sacc[i][e] = 0.0f;
        #pragma unroll
        for (int k8 = 0; k8 < 8; k8++) {
            #pragma unroll
            for (int nt = 0; nt < 8; nt++) {
                uint32_t b0 = __float_as_uint(Kt[(nt * 8 + g) * 68 + k8 * 8 + tig    ]);
                uint32_t b1 = __float_as_uint(Kt[(nt * 8 + g) * 68 + k8 * 8 + tig + 4]);
                mma_tf32(sacc[nt], qf[k8][0], qf[k8][1], qf[k8][2], qf[k8][3], b0, b1);
            }
        }

        // ---- online softmax (base-2)
        float mx0 = -1e30f, mx1 = -1e30f;
        #pragma unroll
        for (int nt = 0; nt < 8; nt++) {
            mx0 = fmaxf(mx0, fmaxf(sacc[nt][0], sacc[nt][1]));
            mx1 = fmaxf(mx1, fmaxf(sacc[nt][2], sacc[nt][3]));
        }
        mx0 = fmaxf(mx0, __shfl_xor_sync(0xffffffffu, mx0, 1));
        mx0 = fmaxf(mx0, __shfl_xor_sync(0xffffffffu, mx0, 2));
        mx1 = fmaxf(mx1, __shfl_xor_sync(0xffffffffu, mx1, 1));
        mx1 = fmaxf(mx1, __shfl_xor_sync(0xffffffffu, mx1, 2));
        float nm0 = fmaxf(m0r, mx0), nm1 = fmaxf(m1r, mx1);
        float cr0 = ex2(m0r - nm0), cr1 = ex2(m1r - nm1);
        m0r = nm0; m1r = nm1;

        float sum0 = 0.0f, sum1 = 0.0f;
        #pragma unroll
        for (int nt = 0; nt < 8; nt++) {
            sacc[nt][0] = ex2(sacc[nt][0] - nm0);
            sacc[nt][1] = ex2(sacc[nt][1] - nm0);
            sacc[nt][2] = ex2(sacc[nt][2] - nm1);
            sacc[nt][3] = ex2(sacc[nt][3] - nm1);
            sum0 += sacc[nt][0] + sacc[nt][1];
            sum1 += sacc[nt][2] + sacc[nt][3];
        }
        sum0 += __shfl_xor_sync(0xffffffffu, sum0, 1);
        sum0 += __shfl_xor_sync(0xffffffffu, sum0, 2);
        sum1 += __shfl_xor_sync(0xffffffffu, sum1, 1);
        sum1 += __shfl_xor_sync(0xffffffffu, sum1, 2);
        l0r = l0r * cr0 + sum0;
        l1r = l1r * cr1 + sum1;
        #pragma unroll
        for (int nt = 0; nt < 8; nt++) {
            of[nt][0] *= cr0; of[nt][1] *= cr0;
            of[nt][2] *= cr1; of[nt][3] *= cr1;
        }

        // ---- store P (tf32) into this warp's own rows of Pw
        #pragma unroll
        for (int nt = 0; nt < 8; nt++) {
            float2 v01, v23;
            v01.x = __uint_as_float(f2tf32(sacc[nt][0]));
            v01.y = __uint_as_float(f2tf32(sacc[nt][1]));
            v23.x = __uint_as_float(f2tf32(sacc[nt][2]));
            v23.y = __uint_as_float(f2tf32(sacc[nt][3]));
            *(float2*)&Pw[(wrow + g    ) * 68 + nt * 8 + tig * 2] = v01;
            *(float2*)&Pw[(wrow + g + 8) * 68 + nt * 8 + tig * 2] = v23;
        }
        __syncwarp();

        // ---- O += P @ V
        #pragma unroll
        for (int k8 = 0; k8 < 8; k8++) {
            uint32_t a0 = __float_as_uint(Pw[(wrow + g    ) * 68 + k8 * 8 + tig    ]);
            uint32_t a1 = __float_as_uint(Pw[(wrow + g + 8) * 68 + k8 * 8 + tig    ]);
            uint32_t a2 = __float_as_uint(Pw[(wrow + g    ) * 68 + k8 * 8 + tig + 4]);
            uint32_t a3 = __float_as_uint(Pw[(wrow + g + 8) * 68 + k8 * 8 + tig + 4]);
            #pragma unroll
            for (int nt = 0; nt < 8; nt++) {
                uint32_t b0 = __float_as_uint(Vt[(k8 * 8 + tig    ) * 72 + nt * 8 + g]);
                uint32_t b1 = __float_as_uint(Vt[(k8 * 8 + tig + 4) * 72 + nt * 8 + g]);
                mma_tf32(of[nt], a0, a1, a2, a3, b0, b1);
            }
        }
    }

    // ---- epilogue: normalize and write [b, t, n, h]
    const float inv0 = 1.0f / l0r;
    const float inv1 = 1.0f / l1r;
    const int t0 = q0 + wrow + g;
    #pragma unroll
    for (int nt = 0; nt < 8; nt++) {
        const int h = nt * 8 + tig * 2;
        float2 v01, v23;
        v01.x = of[nt][0] * inv0; v01.y = of[nt][1] * inv0;
        v23.x = of[nt][2] * inv1; v23.y = of[nt][3] * inv1;
        *(float2*)(O + (((size_t)b * T_ + t0    ) * NH_ + n) * HD_ + h) = v01;
        *(float2*)(O + (((size_t)b * T_ + t0 + 8) * NH_ + n) * HD_ + h) = v23;
    }
}

// ---------------------------------------------------------------------------
// Launch
// Inputs: 0:q 1:v 2:k 3:w_query 4:b_query 5:w_value 6:b_value 7:w_key 8:b_key
//         9:w_projection 10:b_projection
// ---------------------------------------------------------------------------
extern "C" void kernel_launch(void* const* d_in, const int* in_sizes, int n_in,
                              void* d_out, int out_size)
{
    const float* q_in = (const float*)d_in[0];
    const float* v_in = (const float*)d_in[1];
    const float* k_in = (const float*)d_in[2];
    const float* w_q  = (const float*)d_in[3];
    const float* b_q  = (const float*)d_in[4];
    const float* w_v  = (const float*)d_in[5];
    const float* b_v  = (const float*)d_in[6];
    const float* w_k  = (const float*)d_in[7];
    const float* b_k  = (const float*)d_in[8];
    const float* w_p  = (const float*)d_in[9];
    const float* b_p  = (const float*)d_in[10];
    float* out = (float*)d_out;

    float *gq, *gk, *gv, *gattn, *gwpt;
    cudaGetSymbolAddress((void**)&gq,    g_q);
    cudaGetSymbolAddress((void**)&gk,    g_k);
    cudaGetSymbolAddress((void**)&gv,    g_v);
    cudaGetSymbolAddress((void**)&gattn, g_attn);
    cudaGetSymbolAddress((void**)&gwpt,  g_wpt);

    const int ATTN_SMEM = (64 * 68 + 64 * 72 + 64 * 68) * 4;   // 53248 B
    cudaFuncSetAttribute(attn_tc_kernel,
                         cudaFuncAttributeMaxDynamicSharedMemorySize, ATTN_SMEM);

    // 1. transpose w_projection
    transpose_wp_kernel<<<(NDH_ * D_ + 255) / 256, 256>>>(w_p, gwpt);

    // 2-4. QKV projections (bf16-split tensor core, double-buffered)
    dim3 ggrid(NDH_ / 128, BT_ / 128);   // (8, 32)
    gemm_bf16x2_kernel<0><<<ggrid, 256>>>(q_in, w_q, b_q, gq, BT_, D_, NDH_);
    gemm_bf16x2_kernel<0><<<ggrid, 256>>>(k_in, w_k, b_k, gk, BT_, D_, NDH_);
    gemm_bf16x2_kernel<0><<<ggrid, 256>>>(v_in, w_v, b_v, gv, BT_, D_, NDH_);

    // 5. attention (tf32 tensor core flash attention)
    dim3 agrid(T_ / 64, B_ * NH_);       // (32, 32)
    attn_tc_kernel<<<agrid, 128, ATTN_SMEM>>>(gq, gk, gv, gattn);

    // 6. output projection
    dim3 pgrid(D_ / 128, BT_ / 128);     // (8, 32)
    gemm_bf16x2_kernel<1><<<pgrid, 256>>>(gattn, gwpt, b_p, out, BT_, NDH_, D_);
}

// round 6
// speedup vs baseline: 1.0276x; 1.0034x over previous
#include <cuda_runtime.h>
#include <cuda_bf16.h>
#include <math.h>
#include <stdint.h>

#define B_   2
#define T_   2048
#define D_   1024
#define NH_  16
#define HD_  64
#define BT_  (B_*T_)      // 4096
#define NDH_ (NH_*HD_)    // 1024

// Scratch (allocation-free: __device__ globals)
__device__ float g_q[(size_t)B_*NH_*T_*HD_];     // [b,n,t,h]
__device__ float g_k[(size_t)B_*NH_*T_*HD_];     // [b,n,t,h]
__device__ float g_v[(size_t)B_*NH_*T_*HD_];     // [b,n,t,h]
__device__ float g_attn[(size_t)BT_*NDH_];       // [b,t,n,h]
__device__ float g_wpt[(size_t)NDH_*D_];         // [(n,h), d]

// ---------------------------------------------------------------------------
// helpers
// ---------------------------------------------------------------------------
__device__ __forceinline__ uint32_t f2tf32(float x) {
    uint32_t r;
    asm("cvt.rna.tf32.f32 %0, %1;" : "=r"(r) : "f"(x));
    return r;
}

__device__ __forceinline__ float ex2(float x) {
    float r;
    asm("ex2.approx.f32 %0, %1;" : "=f"(r) : "f"(x));
    return r;
}

__device__ __forceinline__ void mma_tf32(float* c,
                                         uint32_t a0, uint32_t a1, uint32_t a2, uint32_t a3,
                                         uint32_t b0, uint32_t b1) {
    asm volatile("mma.sync.aligned.m16n8k8.row.col.f32.tf32.tf32.f32 "
                 "{%0,%1,%2,%3}, {%4,%5,%6,%7}, {%8,%9}, {%0,%1,%2,%3};"
                 : "+f"(c[0]), "+f"(c[1]), "+f"(c[2]), "+f"(c[3])
                 : "r"(a0), "r"(a1), "r"(a2), "r"(a3), "r"(b0), "r"(b1));
}

__device__ __forceinline__ void mma_bf16(float* c,
                                         uint32_t a0, uint32_t a1, uint32_t a2, uint32_t a3,
                                         uint32_t b0, uint32_t b1) {
    asm volatile("mma.sync.aligned.m16n8k16.row.col.f32.bf16.bf16.f32 "
                 "{%0,%1,%2,%3}, {%4,%5,%6,%7}, {%8,%9}, {%0,%1,%2,%3};"
                 : "+f"(c[0]), "+f"(c[1]), "+f"(c[2]), "+f"(c[3])
                 : "r"(a0), "r"(a1), "r"(a2), "r"(a3), "r"(b0), "r"(b1));
}

// split two fp32 (even,odd along k) into packed bf16x2 hi and lo parts
__device__ __forceinline__ void split2(float e, float o, uint32_t& hi, uint32_t& lo) {
    __nv_bfloat162 h = __floats2bfloat162_rn(e, o);
    float he = __low2float(h), ho = __high2float(h);
    __nv_bfloat162 l = __floats2bfloat162_rn(e - he, o - ho);
    hi = *reinterpret_cast<uint32_t*>(&h);
    lo = *reinterpret_cast<uint32_t*>(&l);
}

// ---------------------------------------------------------------------------
// Transpose w_projection [N, D, H] -> [(n,h), d]
// ---------------------------------------------------------------------------
__global__ void transpose_wp_kernel(const float* __restrict__ wp,
                                    float* __restrict__ wpt)
{
    int idx = blockIdx.x * blockDim.x + threadIdx.x;
    if (idx >= NDH_ * D_) return;
    int d = idx % D_;
    int k = idx / D_;
    int n = k / HD_;
    int h = k % HD_;
    wpt[idx] = wp[((size_t)n * D_ + d) * HD_ + h];
}

// ---------------------------------------------------------------------------
// bf16-split tensor-core GEMM, double-buffered smem, 1 sync per k-tile.
// 128x128 block tile, BK=16, 8 warps (2 M x 4 N), warp tile 64x32.
// MODE 0: C -> [B, N, T, H];  MODE 1: C -> [M, Ncols] row-major.
// ---------------------------------------------------------------------------
template<int MODE>
__global__ __launch_bounds__(256)
void gemm_bf16x2_kernel(const float* __restrict__ A,
                        const float* __restrict__ Bm,
                        const float* __restrict__ bias,
                        float* __restrict__ C,
                        int M, int K, int Ncols)
{
    __shared__ uint32_t AsHi[2][8][136];
    __shared__ uint32_t AsLo[2][8][136];
    __shared__ uint32_t BsHi[2][8][136];
    __shared__ uint32_t BsLo[2][8][136];

    const int tid  = threadIdx.x;
    const int warp = tid >> 5;
    const int lane = tid & 31;
    const int g    = lane >> 2;
    const int tig  = lane & 3;
    const int wm   = warp >> 2;   // 0..1  (64 rows each)
    const int wn   = warp & 3;    // 0..3  (32 cols each)
    const int m0   = blockIdx.y * 128;
    const int n0   = blockIdx.x * 128;

    const int la_m    = tid >> 1;        // 0..127
    const int la_half = tid & 1;         // k-half: 0 or 1 (8 floats each)
    const int lb_pr   = tid >> 5;        // 0..7 (pair-row)
    const int lb_n4   = (tid & 31) << 2; // 0..124

    float acc[4][4][4];
    #pragma unroll
    for (int i = 0; i < 4; i++)
        #pragma unroll
        for (int j = 0; j < 4; j++)
            #pragma unroll
            for (int e = 0; e < 4; e++)
                acc[i][j][e] = 0.0f;

    float4 ar0, ar1, br0, br1;

    auto gload = [&](int k0) {
        const float4* a4 = (const float4*)(A + (size_t)(m0 + la_m) * K + k0 + la_half * 8);
        ar0 = a4[0];
        ar1 = a4[1];
        const float* bp = Bm + (size_t)(k0 + 2 * lb_pr) * Ncols + n0 + lb_n4;
        br0 = *(const float4*)bp;
        br1 = *(const float4*)(bp + Ncols);
    };

    auto sstore = [&](int st) {
        uint32_t h, l;
        const int pr = la_half * 4;
        split2(ar0.x, ar0.y, h, l); AsHi[st][pr + 0][la_m] = h; AsLo[st][pr + 0][la_m] = l;
        split2(ar0.z, ar0.w, h, l); AsHi[st][pr + 1][la_m] = h; AsLo[st][pr + 1][la_m] = l;
        split2(ar1.x, ar1.y, h, l); AsHi[st][pr + 2][la_m] = h; AsLo[st][pr + 2][la_m] = l;
        split2(ar1.z, ar1.w, h, l); AsHi[st][pr + 3][la_m] = h; AsLo[st][pr + 3][la_m] = l;
        uint32_t h0, l0, h1, l1, h2, l2, h3, l3;
        split2(br0.x, br1.x, h0, l0);
        split2(br0.y, br1.y, h1, l1);
        split2(br0.z, br1.z, h2, l2);
        split2(br0.w, br1.w, h3, l3);
        *(uint4*)&BsHi[st][lb_pr][lb_n4] = make_uint4(h0, h1, h2, h3);
        *(uint4*)&BsLo[st][lb_pr][lb_n4] = make_uint4(l0, l1, l2, l3);
    };

    auto compute = [&](int st) {
        uint32_t bh[4][2], bl[4][2];
        #pragma unroll
        for (int nt = 0; nt < 4; nt++) {
            const int col = wn * 32 + nt * 8 + g;
            bh[nt][0] = BsHi[st][tig][col];     bh[nt][1] = BsHi[st][tig + 4][col];
            bl[nt][0] = BsLo[st][tig][col];     bl[nt][1] = BsLo[st][tig + 4][col];
        }
        #pragma unroll
        for (int mt = 0; mt < 4; mt++) {
            const int rb = wm * 64 + mt * 16;
            uint32_t ah0 = AsHi[st][tig][rb + g],     ah1 = AsHi[st][tig][rb + g + 8];
            uint32_t ah2 = AsHi[st][tig + 4][rb + g], ah3 = AsHi[st][tig + 4][rb + g + 8];
            uint32_t al0 = AsLo[st][tig][rb + g],     al1 = AsLo[st][tig][rb + g + 8];
            uint32_t al2 = AsLo[st][tig + 4][rb + g], al3 = AsLo[st][tig + 4][rb + g + 8];
            #pragma unroll
            for (int nt = 0; nt < 4; nt++) {
                mma_bf16(acc[mt][nt], ah0, ah1, ah2, ah3, bh[nt][0], bh[nt][1]);
                mma_bf16(acc[mt][nt], ah0, ah1, ah2, ah3, bl[nt][0], bl[nt][1]);
                mma_bf16(acc[mt][nt], al0, al1, al2, al3, bh[nt][0], bh[nt][1]);
            }
        }
    };

    // prologue
    gload(0);
    sstore(0);
    __syncthreads();

    int st = 0;
    for (int k0 = 16; k0 < K; k0 += 16) {
        gload(k0);          // prefetch next tile (LDGs fly during MMAs)
        compute(st);
        sstore(st ^ 1);
        __syncthreads();
        st ^= 1;
    }
    compute(st);

    // ---- epilogue
    #pragma unroll
    for (int mt = 0; mt < 4; mt++) {
        #pragma unroll
        for (int nt = 0; nt < 4; nt++) {
            const int cbase = n0 + wn * 32 + nt * 8 + tig * 2;
            #pragma unroll
            for (int e = 0; e < 4; e++) {
                const int m  = m0 + wm * 64 + mt * 16 + g + ((e >= 2) ? 8 : 0);
                const int cc = cbase + (e & 1);
                float val = acc[mt][nt][e] + bias[cc];
                if (MODE == 0) {
                    int b = m >> 11, t = m & (T_ - 1);
                    int n = cc >> 6, h = cc & 63;
                    C[(((size_t)b * NH_ + n) * T_ + t) * HD_ + h] = val;
                } else {
                    C[(size_t)m * Ncols + cc] = val;
                }
            }
        }
    }
}

// ---------------------------------------------------------------------------
// tf32 tensor-core flash attention (dedicated P buffer, exp2 softmax).
// Block = 128 threads (4 warps), 64 query rows of one (b, head); warp owns 16.
// Dynamic smem: K[64][68] + V[64][72] + P[64][68] = 53248 B -> 4 CTAs/SM.
// 2 syncthreads per 64-key tile. Output written to [b, t, n, h].
// ---------------------------------------------------------------------------
__global__ __launch_bounds__(128, 4)
void attn_tc_kernel(const float* __restrict__ Q,
                    const float* __restrict__ K,
                    const float* __restrict__ V,
                    float* __restrict__ O)
{
    extern __shared__ float smx[];
    float* Kt = smx;                 // [64][68] tf32 bits
    float* Vt = smx + 64 * 68;       // [64][72] tf32 bits
    float* Pw = Vt  + 64 * 72;       // [64][68] per-warp P (also Q staging)

    const int tid  = threadIdx.x;
    const int warp = tid >> 5;
    const int lane = tid & 31;
    const int g    = lane >> 2;
    const int tig  = lane & 3;
    const int bn   = blockIdx.y;        // b*NH + n
    const int b    = bn / NH_;
    const int n    = bn % NH_;
    const int q0   = blockIdx.x * 64;
    const int wrow = warp * 16;

    const float* Qg = Q + ((size_t)bn * T_ + q0) * HD_;
    const float* Kg = K + (size_t)bn * T_ * HD_;
    const float* Vg = V + (size_t)bn * T_ * HD_;

    // ---- stage Q tile into Pw, then load persistent A-fragments
    #pragma unroll
    for (int i = 0; i < 8; i++) {
        int lin = tid + i * 128;          // float4 slots over 64x16
        int r = lin >> 4, c4 = (lin & 15) << 2;
        float4 v4 = *(const float4*)(Qg + r * HD_ + c4);
        Pw[r * 68 + c4 + 0] = v4.x; Pw[r * 68 + c4 + 1] = v4.y;
        Pw[r * 68 + c4 + 2] = v4.z; Pw[r * 68 + c4 + 3] = v4.w;
    }
    __syncthreads();
    // scale folds 1/sqrt(H) and log2(e) so softmax uses raw ex2
    const float qs = 0.125f * 1.4426950408889634f;
    uint32_t qf[8][4];
    #pragma unroll
    for (int k8 = 0; k8 < 8; k8++) {
        qf[k8][0] = f2tf32(Pw[(wrow + g    ) * 68 + k8 * 8 + tig    ] * qs);
        qf[k8][1] = f2tf32(Pw[(wrow + g + 8) * 68 + k8 * 8 + tig    ] * qs);
        qf[k8][2] = f2tf32(Pw[(wrow + g    ) * 68 + k8 * 8 + tig + 4] * qs);
        qf[k8][3] = f2tf32(Pw[(wrow + g + 8) * 68 + k8 * 8 + tig + 4] * qs);
    }

    float of[8][4];
    #pragma unroll
    for (int i = 0; i < 8; i++)
        #pragma unroll
        for (int e = 0; e < 4; e++) of[i][e] = 0.0f;
    float m0r = -1e30f, m1r = -1e30f;
    float l0r = 0.0f,   l1r = 0.0f;

    for (int s0 = 0; s0 < T_; s0 += 64) {
        __syncthreads();   // all warps done reading Kt/Vt of previous tile
        // ---- load K -> Kt, V -> Vt (convert to tf32)
        #pragma unroll
        for (int i = 0; i < 8; i++) {
            int lin = tid + i * 128;
            int r = lin >> 4, c4 = (lin & 15) << 2;
            float4 kv = *(const float4*)(Kg + (size_t)(s0 + r) * HD_ + c4);
            float4 vv = *(const float4*)(Vg + (size_t)(s0 + r) * HD_ + c4);
            Kt[r * 68 + c4 + 0] = __uint_as_float(f2tf32(kv.x));
            Kt[r * 68 + c4 + 1] = __uint_as_float(f2tf32(kv.y));
            Kt[r * 68 + c4 + 2] = __uint_as_float(f2tf32(kv.z));
            Kt[r * 68 + c4 + 3] = __uint_as_float(f2tf32(kv.w));
            Vt[r * 72 + c4 + 0] = __uint_as_float(f2tf32(vv.x));
            Vt[r * 72 + c4 + 1] = __uint_as_float(f2tf32(vv.y));
            Vt[r * 72 + c4 + 2] = __uint_as_float(f2tf32(vv.z));
            Vt[r * 72 + c4 + 3] = __uint_as_float(f2tf32(vv.w));
        }
        __syncthreads();

        // ---- S = (Q*qs) @ K^T  (scores in log2 domain)
        float sacc[8][4];
        #pragma unroll
        for (int i = 0; i < 8; i++)
            #pragma unroll
            for (int e = 0; e < 4; e++) sacc[i][e] = 0.0f;
        #pragma unroll
        for (int k8 = 0; k8 < 8; k8++) {
            #pragma unroll
            for (int nt = 0; nt < 8; nt++) {
                uint32_t b0 = __float_as_uint(Kt[(nt * 8 + g) * 68 + k8 * 8 + tig    ]);
                uint32_t b1 = __float_as_uint(Kt[(nt * 8 + g) * 68 + k8 * 8 + tig + 4]);
                mma_tf32(sacc[nt], qf[k8][0], qf[k8][1], qf[k8][2], qf[k8][3], b0, b1);
            }
        }

        // ---- online softmax (base-2)
        float mx0 = -1e30f, mx1 = -1e30f;
        #pragma unroll
        for (int nt = 0; nt < 8; nt++) {
            mx0 = fmaxf(mx0, fmaxf(sacc[nt][0], sacc[nt][1]));
            mx1 = fmaxf(mx1, fmaxf(sacc[nt][2], sacc[nt][3]));
        }
        mx0 = fmaxf(mx0, __shfl_xor_sync(0xffffffffu, mx0, 1));
        mx0 = fmaxf(mx0, __shfl_xor_sync(0xffffffffu, mx0, 2));
        mx1 = fmaxf(mx1, __shfl_xor_sync(0xffffffffu, mx1, 1));
        mx1 = fmaxf(mx1, __shfl_xor_sync(0xffffffffu, mx1, 2));
        float nm0 = fmaxf(m0r, mx0), nm1 = fmaxf(m1r, mx1);
        float cr0 = ex2(m0r - nm0), cr1 = ex2(m1r - nm1);
        m0r = nm0; m1r = nm1;

        float sum0 = 0.0f, sum1 = 0.0f;
        #pragma unroll
        for (int nt = 0; nt < 8; nt++) {
            sacc[nt][0] = ex2(sacc[nt][0] - nm0);
            sacc[nt][1] = ex2(sacc[nt][1] - nm0);
            sacc[nt][2] = ex2(sacc[nt][2] - nm1);
            sacc[nt][3] = ex2(sacc[nt][3] - nm1);
            sum0 += sacc[nt][0] + sacc[nt][1];
            sum1 += sacc[nt][2] + sacc[nt][3];
        }
        sum0 += __shfl_xor_sync(0xffffffffu, sum0, 1);
        sum0 += __shfl_xor_sync(0xffffffffu, sum0, 2);
        sum1 += __shfl_xor_sync(0xffffffffu, sum1, 1);
        sum1 += __shfl_xor_sync(0xffffffffu, sum1, 2);
        l0r = l0r * cr0 + sum0;
        l1r = l1r * cr1 + sum1;
        #pragma unroll
        for (int nt = 0; nt < 8; nt++) {
            of[nt][0] *= cr0; of[nt][1] *= cr0;
            of[nt][2] *= cr1; of[nt][3] *= cr1;
        }

        // ---- store P (tf32) into this warp's own rows of Pw
        #pragma unroll
        for (int nt = 0; nt < 8; nt++) {
            float2 v01, v23;
            v01.x = __uint_as_float(f2tf32(sacc[nt][0]));
            v01.y = __uint_as_float(f2tf32(sacc[nt][1]));
            v23.x = __uint_as_float(f2tf32(sacc[nt][2]));
            v23.y = __uint_as_float(f2tf32(sacc[nt][3]));
            *(float2*)&Pw[(wrow + g    ) * 68 + nt * 8 + tig * 2] = v01;
            *(float2*)&Pw[(wrow + g + 8) * 68 + nt * 8 + tig * 2] = v23;
        }
        __syncwarp();

        // ---- O += P @ V
        #pragma unroll
        for (int k8 = 0; k8 < 8; k8++) {
            uint32_t a0 = __float_as_uint(Pw[(wrow + g    ) * 68 + k8 * 8 + tig    ]);
            uint32_t a1 = __float_as_uint(Pw[(wrow + g + 8) * 68 + k8 * 8 + tig    ]);
            uint32_t a2 = __float_as_uint(Pw[(wrow + g    ) * 68 + k8 * 8 + tig + 4]);
            uint32_t a3 = __float_as_uint(Pw[(wrow + g + 8) * 68 + k8 * 8 + tig + 4]);
            #pragma unroll
            for (int nt = 0; nt < 8; nt++) {
                uint32_t b0 = __float_as_uint(Vt[(k8 * 8 + tig    ) * 72 + nt * 8 + g]);
                uint32_t b1 = __float_as_uint(Vt[(k8 * 8 + tig + 4) * 72 + nt * 8 + g]);
                mma_tf32(of[nt], a0, a1, a2, a3, b0, b1);
            }
        }
    }

    // ---- epilogue: normalize and write [b, t, n, h]
    const float inv0 = 1.0f / l0r;
    const float inv1 = 1.0f / l1r;
    const int t0 = q0 + wrow + g;
    #pragma unroll
    for (int nt = 0; nt < 8; nt++) {
        const int h = nt * 8 + tig * 2;
        float2 v01, v23;
        v01.x = of[nt][0] * inv0; v01.y = of[nt][1] * inv0;
        v23.x = of[nt][2] * inv1; v23.y = of[nt][3] * inv1;
        *(float2*)(O + (((size_t)b * T_ + t0    ) * NH_ + n) * HD_ + h) = v01;
        *(float2*)(O + (((size_t)b * T_ + t0 + 8) * NH_ + n) * HD_ + h) = v23;
    }
}

// ---------------------------------------------------------------------------
// Launch
// Inputs: 0:q 1:v 2:k 3:w_query 4:b_query 5:w_value 6:b_value 7:w_key 8:b_key
//         9:w_projection 10:b_projection
// ---------------------------------------------------------------------------
extern "C" void kernel_launch(void* const* d_in, const int* in_sizes, int n_in,
                              void* d_out, int out_size)
{
    const float* q_in = (const float*)d_in[0];
    const float* v_in = (const float*)d_in[1];
    const float* k_in = (const float*)d_in[2];
    const float* w_q  = (const float*)d_in[3];
    const float* b_q  = (const float*)d_in[4];
    const float* w_v  = (const float*)d_in[5];
    const float* b_v  = (const float*)d_in[6];
    const float* w_k  = (const float*)d_in[7];
    const float* b_k  = (const float*)d_in[8];
    const float* w_p  = (const float*)d_in[9];
    const float* b_p  = (const float*)d_in[10];
    float* out = (float*)d_out;

    float *gq, *gk, *gv, *gattn, *gwpt;
    cudaGetSymbolAddress((void**)&gq,    g_q);
    cudaGetSymbolAddress((void**)&gk,    g_k);
    cudaGetSymbolAddress((void**)&gv,    g_v);
    cudaGetSymbolAddress((void**)&gattn, g_attn);
    cudaGetSymbolAddress((void**)&gwpt,  g_wpt);

    const int ATTN_SMEM = (64 * 68 + 64 * 72 + 64 * 68) * 4;   // 53248 B
    cudaFuncSetAttribute(attn_tc_kernel,
                         cudaFuncAttributeMaxDynamicSharedMemorySize, ATTN_SMEM);

    // 1. transpose w_projection
    transpose_wp_kernel<<<(NDH_ * D_ + 255) / 256, 256>>>(w_p, gwpt);

    // 2-4. QKV projections (bf16-split tensor core, double-buffered)
    dim3 ggrid(NDH_ / 128, BT_ / 128);   // (8, 32)
    gemm_bf16x2_kernel<0><<<ggrid, 256>>>(q_in, w_q, b_q, gq, BT_, D_, NDH_);
    gemm_bf16x2_kernel<0><<<ggrid, 256>>>(k_in, w_k, b_k, gk, BT_, D_, NDH_);
    gemm_bf16x2_kernel<0><<<ggrid, 256>>>(v_in, w_v, b_v, gv, BT_, D_, NDH_);

    // 5. attention (tf32 tensor core flash attention)
    dim3 agrid(T_ / 64, B_ * NH_);       // (32, 32)
    attn_tc_kernel<<<agrid, 128, ATTN_SMEM>>>(gq, gk, gv, gattn);

    // 6. output projection
    dim3 pgrid(D_ / 128, BT_ / 128);     // (8, 32)
    gemm_bf16x2_kernel<1><<<pgrid, 256>>>(gattn, gwpt, b_p, out, BT_, NDH_, D_);
}

// round 7
// speedup vs baseline: 1.0698x; 1.0411x over previous
#include <cuda_runtime.h>
#include <cuda_bf16.h>
#include <math.h>
#include <stdint.h>

#define B_   2
#define T_   2048
#define D_   1024
#define NH_  16
#define HD_  64
#define BT_  (B_*T_)      // 4096
#define NDH_ (NH_*HD_)    // 1024

// Scratch (allocation-free: __device__ globals)
__device__ float g_q[(size_t)B_*NH_*T_*HD_];     // [b,n,t,h]
__device__ float g_k[(size_t)B_*NH_*T_*HD_];     // [b,n,t,h]
__device__ float g_v[(size_t)B_*NH_*T_*HD_];     // [b,n,t,h]
__device__ float g_attn[(size_t)BT_*NDH_];       // [b,t,n,h]

// prepacked weights: [K/2][N] uint32 = (bf16 even-k, bf16 odd-k)
__device__ uint32_t g_wq_hi[(size_t)(D_/2)*NDH_], g_wq_lo[(size_t)(D_/2)*NDH_];
__device__ uint32_t g_wk_hi[(size_t)(D_/2)*NDH_], g_wk_lo[(size_t)(D_/2)*NDH_];
__device__ uint32_t g_wv_hi[(size_t)(D_/2)*NDH_], g_wv_lo[(size_t)(D_/2)*NDH_];
__device__ uint32_t g_wp_hi[(size_t)(NDH_/2)*D_], g_wp_lo[(size_t)(NDH_/2)*D_];

// ---------------------------------------------------------------------------
// helpers
// ---------------------------------------------------------------------------
__device__ __forceinline__ uint32_t f2tf32(float x) {
    uint32_t r;
    asm("cvt.rna.tf32.f32 %0, %1;" : "=r"(r) : "f"(x));
    return r;
}

__device__ __forceinline__ float ex2(float x) {
    float r;
    asm("ex2.approx.f32 %0, %1;" : "=f"(r) : "f"(x));
    return r;
}

__device__ __forceinline__ void mma_tf32(float* c,
                                         uint32_t a0, uint32_t a1, uint32_t a2, uint32_t a3,
                                         uint32_t b0, uint32_t b1) {
    asm volatile("mma.sync.aligned.m16n8k8.row.col.f32.tf32.tf32.f32 "
                 "{%0,%1,%2,%3}, {%4,%5,%6,%7}, {%8,%9}, {%0,%1,%2,%3};"
                 : "+f"(c[0]), "+f"(c[1]), "+f"(c[2]), "+f"(c[3])
                 : "r"(a0), "r"(a1), "r"(a2), "r"(a3), "r"(b0), "r"(b1));
}

__device__ __forceinline__ void mma_bf16(float* c,
                                         uint32_t a0, uint32_t a1, uint32_t a2, uint32_t a3,
                                         uint32_t b0, uint32_t b1) {
    asm volatile("mma.sync.aligned.m16n8k16.row.col.f32.bf16.bf16.f32 "
                 "{%0,%1,%2,%3}, {%4,%5,%6,%7}, {%8,%9}, {%0,%1,%2,%3};"
                 : "+f"(c[0]), "+f"(c[1]), "+f"(c[2]), "+f"(c[3])
                 : "r"(a0), "r"(a1), "r"(a2), "r"(a3), "r"(b0), "r"(b1));
}

// split two fp32 (even,odd along k) into packed bf16x2 hi and lo parts
__device__ __forceinline__ void split2(float e, float o, uint32_t& hi, uint32_t& lo) {
    __nv_bfloat162 h = __floats2bfloat162_rn(e, o);
    float he = __low2float(h), ho = __high2float(h);
    __nv_bfloat162 l = __floats2bfloat162_rn(e - he, o - ho);
    hi = *reinterpret_cast<uint32_t*>(&h);
    lo = *reinterpret_cast<uint32_t*>(&l);
}

// ---------------------------------------------------------------------------
// Prepack W [K][N] fp32 -> hi/lo [K/2][N] uint32 (bf16 pair along k)
// ---------------------------------------------------------------------------
__global__ void prepack_w_kernel(const float* __restrict__ W,
                                 uint32_t* __restrict__ hi,
                                 uint32_t* __restrict__ lo,
                                 int K2, int N)
{
    int idx = blockIdx.x * blockDim.x + threadIdx.x;
    if (idx >= K2 * N) return;
    int k2 = idx / N, n = idx % N;
    float e = W[(size_t)(2 * k2) * N + n];
    float o = W[(size_t)(2 * k2 + 1) * N + n];
    uint32_t h, l;
    split2(e, o, h, l);
    hi[idx] = h;
    lo[idx] = l;
}

// ---------------------------------------------------------------------------
// Prepack w_projection [N, D, H] -> transposed [(n,h)/2][d] hi/lo pairs
// (pairs are (h even, h odd) within the same head: always valid since H=64)
// ---------------------------------------------------------------------------
__global__ void prepack_wpt_kernel(const float* __restrict__ wp,
                                   uint32_t* __restrict__ hi,
                                   uint32_t* __restrict__ lo)
{
    int idx = blockIdx.x * blockDim.x + threadIdx.x;   // 16*1024*32 = 524288
    if (idx >= (NDH_ / 2) * D_) return;
    int hp = idx & 31;              // h pair index, h = 2*hp
    int d  = (idx >> 5) & (D_ - 1);
    int n  = idx >> 15;             // 0..15
    const float* base = wp + ((size_t)n * D_ + d) * HD_ + 2 * hp;
    float e = base[0], o = base[1];
    uint32_t h, l;
    split2(e, o, h, l);
    int k2 = n * (HD_ / 2) + hp;
    hi[(size_t)k2 * D_ + d] = h;
    lo[(size_t)k2 * D_ + d] = l;
}

// ---------------------------------------------------------------------------
// bf16-split tensor-core GEMM core. A fp32 [M,K]; B prepacked hi/lo [K/2][N].
// 128x128 block tile, BK=16, 8 warps (2 M x 4 N), double-buffered smem.
// MODE 0: C -> [B, N, T, H];  MODE 1: C -> [M, Ncols] row-major.
// ---------------------------------------------------------------------------
template<int MODE>
__device__ __forceinline__ void gemm_core(const float* __restrict__ A,
                                          const uint32_t* __restrict__ Bhi,
                                          const uint32_t* __restrict__ Blo,
                                          const float* __restrict__ bias,
                                          float* __restrict__ C,
                                          int M, int K, int Ncols)
{
    __shared__ uint32_t AsHi[2][8][136];
    __shared__ uint32_t AsLo[2][8][136];
    __shared__ uint32_t BsHi[2][8][136];
    __shared__ uint32_t BsLo[2][8][136];

    const int tid  = threadIdx.x;
    const int warp = tid >> 5;
    const int lane = tid & 31;
    const int g    = lane >> 2;
    const int tig  = lane & 3;
    const int wm   = warp >> 2;   // 0..1  (64 rows each)
    const int wn   = warp & 3;    // 0..3  (32 cols each)
    const int m0   = blockIdx.y * 128;
    const int n0   = blockIdx.x * 128;

    const int la_m    = tid >> 1;        // 0..127
    const int la_half = tid & 1;         // k-half: 0 or 1 (8 floats each)
    const int lb_pr   = tid >> 5;        // 0..7 (pair-row)
    const int lb_n4   = (tid & 31) << 2; // 0..124

    float acc[4][4][4];
    #pragma unroll
    for (int i = 0; i < 4; i++)
        #pragma unroll
        for (int j = 0; j < 4; j++)
            #pragma unroll
            for (int e = 0; e < 4; e++)
                acc[i][j][e] = 0.0f;

    float4 ar0, ar1;
    uint4  brh, brl;

    auto gload = [&](int k0) {
        const float4* a4 = (const float4*)(A + (size_t)(m0 + la_m) * K + k0 + la_half * 8);
        ar0 = a4[0];
        ar1 = a4[1];
        const size_t boff = ((size_t)(k0 >> 1) + lb_pr) * Ncols + n0 + lb_n4;
        brh = *(const uint4*)(Bhi + boff);
        brl = *(const uint4*)(Blo + boff);
    };

    auto sstore = [&](int st) {
        uint32_t h, l;
        const int pr = la_half * 4;
        split2(ar0.x, ar0.y, h, l); AsHi[st][pr + 0][la_m] = h; AsLo[st][pr + 0][la_m] = l;
        split2(ar0.z, ar0.w, h, l); AsHi[st][pr + 1][la_m] = h; AsLo[st][pr + 1][la_m] = l;
        split2(ar1.x, ar1.y, h, l); AsHi[st][pr + 2][la_m] = h; AsLo[st][pr + 2][la_m] = l;
        split2(ar1.z, ar1.w, h, l); AsHi[st][pr + 3][la_m] = h; AsLo[st][pr + 3][la_m] = l;
        *(uint4*)&BsHi[st][lb_pr][lb_n4] = brh;
        *(uint4*)&BsLo[st][lb_pr][lb_n4] = brl;
    };

    auto compute = [&](int st) {
        uint32_t bh[4][2], bl[4][2];
        #pragma unroll
        for (int nt = 0; nt < 4; nt++) {
            const int col = wn * 32 + nt * 8 + g;
            bh[nt][0] = BsHi[st][tig][col];     bh[nt][1] = BsHi[st][tig + 4][col];
            bl[nt][0] = BsLo[st][tig][col];     bl[nt][1] = BsLo[st][tig + 4][col];
        }
        #pragma unroll
        for (int mt = 0; mt < 4; mt++) {
            const int rb = wm * 64 + mt * 16;
            uint32_t ah0 = AsHi[st][tig][rb + g],     ah1 = AsHi[st][tig][rb + g + 8];
            uint32_t ah2 = AsHi[st][tig + 4][rb + g], ah3 = AsHi[st][tig + 4][rb + g + 8];
            uint32_t al0 = AsLo[st][tig][rb + g],     al1 = AsLo[st][tig][rb + g + 8];
            uint32_t al2 = AsLo[st][tig + 4][rb + g], al3 = AsLo[st][tig + 4][rb + g + 8];
            #pragma unroll
            for (int nt = 0; nt < 4; nt++) {
                mma_bf16(acc[mt][nt], ah0, ah1, ah2, ah3, bh[nt][0], bh[nt][1]);
                mma_bf16(acc[mt][nt], ah0, ah1, ah2, ah3, bl[nt][0], bl[nt][1]);
                mma_bf16(acc[mt][nt], al0, al1, al2, al3, bh[nt][0], bh[nt][1]);
            }
        }
    };

    // prologue
    gload(0);
    sstore(0);
    __syncthreads();

    int st = 0;
    for (int k0 = 16; k0 < K; k0 += 16) {
        gload(k0);          // prefetch next tile (LDGs fly during MMAs)
        compute(st);
        sstore(st ^ 1);
        __syncthreads();
        st ^= 1;
    }
    compute(st);

    // ---- epilogue
    #pragma unroll
    for (int mt = 0; mt < 4; mt++) {
        #pragma unroll
        for (int nt = 0; nt < 4; nt++) {
            const int cbase = n0 + wn * 32 + nt * 8 + tig * 2;
            #pragma unroll
            for (int e = 0; e < 4; e++) {
                const int m  = m0 + wm * 64 + mt * 16 + g + ((e >= 2) ? 8 : 0);
                const int cc = cbase + (e & 1);
                float val = acc[mt][nt][e] + bias[cc];
                if (MODE == 0) {
                    int b = m >> 11, t = m & (T_ - 1);
                    int n = cc >> 6, h = cc & 63;
                    C[(((size_t)b * NH_ + n) * T_ + t) * HD_ + h] = val;
                } else {
                    C[(size_t)m * Ncols + cc] = val;
                }
            }
        }
    }
}

// Batched QKV projection: blockIdx.z selects q / k / v
__global__ __launch_bounds__(256)
void gemm_qkv_kernel(const float* __restrict__ Aq, const float* __restrict__ Ak,
                     const float* __restrict__ Av,
                     const float* __restrict__ bq, const float* __restrict__ bk,
                     const float* __restrict__ bv,
                     float* __restrict__ Cq, float* __restrict__ Ck,
                     float* __restrict__ Cv)
{
    const int z = blockIdx.z;
    const float*    A    = (z == 0) ? Aq : (z == 1) ? Ak : Av;
    const uint32_t* Bhi  = (z == 0) ? g_wq_hi : (z == 1) ? g_wk_hi : g_wv_hi;
    const uint32_t* Blo  = (z == 0) ? g_wq_lo : (z == 1) ? g_wk_lo : g_wv_lo;
    const float*    bias = (z == 0) ? bq : (z == 1) ? bk : bv;
    float*          C    = (z == 0) ? Cq : (z == 1) ? Ck : Cv;
    gemm_core<0>(A, Bhi, Blo, bias, C, BT_, D_, NDH_);
}

__global__ __launch_bounds__(256)
void gemm_out_kernel(const float* __restrict__ A, const float* __restrict__ bias,
                     float* __restrict__ C)
{
    gemm_core<1>(A, g_wp_hi, g_wp_lo, bias, C, BT_, NDH_, D_);
}

// ---------------------------------------------------------------------------
// tf32 tensor-core flash attention.
// Block = 256 threads (8 warps), 128 query rows of one (b, head); warp owns 16.
// K/V tiles of 64 keys shared by all 8 warps (halves per-head K/V L2 traffic
// vs 64-row q-tiles). Dynamic smem: K[64][68] + V[64][72] + P[128][68] =
// 70656 B -> 2 CTAs/SM. Output written to [b, t, n, h].
// ---------------------------------------------------------------------------
__global__ __launch_bounds__(256, 2)
void attn_tc_kernel(const float* __restrict__ Q,
                    const float* __restrict__ K,
                    const float* __restrict__ V,
                    float* __restrict__ O)
{
    extern __shared__ float smx[];
    float* Kt = smx;                 // [64][68] tf32 bits
    float* Vt = smx + 64 * 68;       // [64][72] tf32 bits
    float* Pw = Vt  + 64 * 72;       // [128][68] per-warp P (also Q staging)

    const int tid  = threadIdx.x;
    const int warp = tid >> 5;
    const int lane = tid & 31;
    const int g    = lane >> 2;
    const int tig  = lane & 3;
    const int bn   = blockIdx.y;        // b*NH + n
    const int b    = bn / NH_;
    const int n    = bn % NH_;
    const int q0   = blockIdx.x * 128;
    const int wrow = warp * 16;         // 0..112

    const float* Qg = Q + ((size_t)bn * T_ + q0) * HD_;
    const float* Kg = K + (size_t)bn * T_ * HD_;
    const float* Vg = V + (size_t)bn * T_ * HD_;

    // ---- stage Q tile (128 x 64) into Pw, then load persistent A-fragments
    #pragma unroll
    for (int i = 0; i < 8; i++) {
        int lin = tid + i * 256;          // float4 slots over 128x16
        int r = lin >> 4, c4 = (lin & 15) << 2;
        float4 v4 = *(const float4*)(Qg + r * HD_ + c4);
        Pw[r * 68 + c4 + 0] = v4.x; Pw[r * 68 + c4 + 1] = v4.y;
        Pw[r * 68 + c4 + 2] = v4.z; Pw[r * 68 + c4 + 3] = v4.w;
    }
    __syncthreads();
    // scale folds 1/sqrt(H) and log2(e) so softmax uses raw ex2
    const float qs = 0.125f * 1.4426950408889634f;
    uint32_t qf[8][4];
    #pragma unroll
    for (int k8 = 0; k8 < 8; k8++) {
        qf[k8][0] = f2tf32(Pw[(wrow + g    ) * 68 + k8 * 8 + tig    ] * qs);
        qf[k8][1] = f2tf32(Pw[(wrow + g + 8) * 68 + k8 * 8 + tig    ] * qs);
        qf[k8][2] = f2tf32(Pw[(wrow + g    ) * 68 + k8 * 8 + tig + 4] * qs);
        qf[k8][3] = f2tf32(Pw[(wrow + g + 8) * 68 + k8 * 8 + tig + 4] * qs);
    }

    float of[8][4];
    #pragma unroll
    for (int i = 0; i < 8; i++)
        #pragma unroll
        for (int e = 0; e < 4; e++) of[i][e] = 0.0f;
    float m0r = -1e30f, m1r = -1e30f;
    float l0r = 0.0f,   l1r = 0.0f;

    for (int s0 = 0; s0 < T_; s0 += 64) {
        __syncthreads();   // all warps done reading Kt/Vt of previous tile
        // ---- load K -> Kt, V -> Vt (convert to tf32); 64x16 float4 slots
        #pragma unroll
        for (int i = 0; i < 4; i++) {
            int lin = tid + i * 256;
            int r = lin >> 4, c4 = (lin & 15) << 2;
            float4 kv = *(const float4*)(Kg + (size_t)(s0 + r) * HD_ + c4);
            float4 vv = *(const float4*)(Vg + (size_t)(s0 + r) * HD_ + c4);
            Kt[r * 68 + c4 + 0] = __uint_as_float(f2tf32(kv.x));
            Kt[r * 68 + c4 + 1] = __uint_as_float(f2tf32(kv.y));
            Kt[r * 68 + c4 + 2] = __uint_as_float(f2tf32(kv.z));
            Kt[r * 68 + c4 + 3] = __uint_as_float(f2tf32(kv.w));
            Vt[r * 72 + c4 + 0] = __uint_as_float(f2tf32(vv.x));
            Vt[r * 72 + c4 + 1] = __uint_as_float(f2tf32(vv.y));
            Vt[r * 72 + c4 + 2] = __uint_as_float(f2tf32(vv.z));
            Vt[r * 72 + c4 + 3] = __uint_as_float(f2tf32(vv.w));
        }
        __syncthreads();

        // ---- S = (Q*qs) @ K^T  (scores in log2 domain); warp: 16x64
        float sacc[8][4];
        #pragma unroll
        for (int i = 0; i < 8; i++)
            #pragma unroll
            for (int e = 0; e < 4; e++) sacc[i][e] = 0.0f;
        #pragma unroll
        for (int k8 = 0; k8 < 8; k8++) {
            #pragma unroll
            for (int nt = 0; nt < 8; nt++) {
                uint32_t b0 = __float_as_uint(Kt[(nt * 8 + g) * 68 + k8 * 8 + tig    ]);
                uint32_t b1 = __float_as_uint(Kt[(nt * 8 + g) * 68 + k8 * 8 + tig + 4]);
                mma_tf32(sacc[nt], qf[k8][0], qf[k8][1], qf[k8][2], qf[k8][3], b0, b1);
            }
        }

        // ---- online softmax (base-2)
        float mx0 = -1e30f, mx1 = -1e30f;
        #pragma unroll
        for (int nt = 0; nt < 8; nt++) {
            mx0 = fmaxf(mx0, fmaxf(sacc[nt][0], sacc[nt][1]));
            mx1 = fmaxf(mx1, fmaxf(sacc[nt][2], sacc[nt][3]));
        }
        mx0 = fmaxf(mx0, __shfl_xor_sync(0xffffffffu, mx0, 1));
        mx0 = fmaxf(mx0, __shfl_xor_sync(0xffffffffu, mx0, 2));
        mx1 = fmaxf(mx1, __shfl_xor_sync(0xffffffffu, mx1, 1));
        mx1 = fmaxf(mx1, __shfl_xor_sync(0xffffffffu, mx1, 2));
        float nm0 = fmaxf(m0r, mx0), nm1 = fmaxf(m1r, mx1);
        float cr0 = ex2(m0r - nm0), cr1 = ex2(m1r - nm1);
        m0r = nm0; m1r = nm1;

        float sum0 = 0.0f, sum1 = 0.0f;
        #pragma unroll
        for (int nt = 0; nt < 8; nt++) {
            sacc[nt][0] = ex2(sacc[nt][0] - nm0);
            sacc[nt][1] = ex2(sacc[nt][1] - nm0);
            sacc[nt][2] = ex2(sacc[nt][2] - nm1);
            sacc[nt][3] = ex2(sacc[nt][3] - nm1);
            sum0 += sacc[nt][0] + sacc[nt][1];
            sum1 += sacc[nt][2] + sacc[nt][3];
        }
        sum0 += __shfl_xor_sync(0xffffffffu, sum0, 1);
        sum0 += __shfl_xor_sync(0xffffffffu, sum0, 2);
        sum1 += __shfl_xor_sync(0xffffffffu, sum1, 1);
        sum1 += __shfl_xor_sync(0xffffffffu, sum1, 2);
        l0r = l0r * cr0 + sum0;
        l1r = l1r * cr1 + sum1;
        #pragma unroll
        for (int nt = 0; nt < 8; nt++) {
            of[nt][0] *= cr0; of[nt][1] *= cr0;
            of[nt][2] *= cr1; of[nt][3] *= cr1;
        }

        // ---- store P (tf32) into this warp's own rows of Pw
        #pragma unroll
        for (int nt = 0; nt < 8; nt++) {
            float2 v01, v23;
            v01.x = __uint_as_float(f2tf32(sacc[nt][0]));
            v01.y = __uint_as_float(f2tf32(sacc[nt][1]));
            v23.x = __uint_as_float(f2tf32(sacc[nt][2]));
            v23.y = __uint_as_float(f2tf32(sacc[nt][3]));
            *(float2*)&Pw[(wrow + g    ) * 68 + nt * 8 + tig * 2] = v01;
            *(float2*)&Pw[(wrow + g + 8) * 68 + nt * 8 + tig * 2] = v23;
        }
        __syncwarp();

        // ---- O += P @ V
        #pragma unroll
        for (int k8 = 0; k8 < 8; k8++) {
            uint32_t a0 = __float_as_uint(Pw[(wrow + g    ) * 68 + k8 * 8 + tig    ]);
            uint32_t a1 = __float_as_uint(Pw[(wrow + g + 8) * 68 + k8 * 8 + tig    ]);
            uint32_t a2 = __float_as_uint(Pw[(wrow + g    ) * 68 + k8 * 8 + tig + 4]);
            uint32_t a3 = __float_as_uint(Pw[(wrow + g + 8) * 68 + k8 * 8 + tig + 4]);
            #pragma unroll
            for (int nt = 0; nt < 8; nt++) {
                uint32_t b0 = __float_as_uint(Vt[(k8 * 8 + tig    ) * 72 + nt * 8 + g]);
                uint32_t b1 = __float_as_uint(Vt[(k8 * 8 + tig + 4) * 72 + nt * 8 + g]);
                mma_tf32(of[nt], a0, a1, a2, a3, b0, b1);
            }
        }
    }

    // ---- epilogue: normalize and write [b, t, n, h]
    const float inv0 = 1.0f / l0r;
    const float inv1 = 1.0f / l1r;
    const int t0 = q0 + wrow + g;
    #pragma unroll
    for (int nt = 0; nt < 8; nt++) {
        const int h = nt * 8 + tig * 2;
        float2 v01, v23;
        v01.x = of[nt][0] * inv0; v01.y = of[nt][1] * inv0;
        v23.x = of[nt][2] * inv1; v23.y = of[nt][3] * inv1;
        *(float2*)(O + (((size_t)b * T_ + t0    ) * NH_ + n) * HD_ + h) = v01;
        *(float2*)(O + (((size_t)b * T_ + t0 + 8) * NH_ + n) * HD_ + h) = v23;
    }
}

// ---------------------------------------------------------------------------
// Launch
// Inputs: 0:q 1:v 2:k 3:w_query 4:b_query 5:w_value 6:b_value 7:w_key 8:b_key
//         9:w_projection 10:b_projection
// ---------------------------------------------------------------------------
extern "C" void kernel_launch(void* const* d_in, const int* in_sizes, int n_in,
                              void* d_out, int out_size)
{
    const float* q_in = (const float*)d_in[0];
    const float* v_in = (const float*)d_in[1];
    const float* k_in = (const float*)d_in[2];
    const float* w_q  = (const float*)d_in[3];
    const float* b_q  = (const float*)d_in[4];
    const float* w_v  = (const float*)d_in[5];
    const float* b_v  = (const float*)d_in[6];
    const float* w_k  = (const float*)d_in[7];
    const float* b_k  = (const float*)d_in[8];
    const float* w_p  = (const float*)d_in[9];
    const float* b_p  = (const float*)d_in[10];
    float* out = (float*)d_out;

    float *gq, *gk, *gv, *gattn;
    uint32_t *wqh, *wql, *wkh, *wkl, *wvh, *wvl, *wph, *wpl;
    cudaGetSymbolAddress((void**)&gq,    g_q);
    cudaGetSymbolAddress((void**)&gk,    g_k);
    cudaGetSymbolAddress((void**)&gv,    g_v);
    cudaGetSymbolAddress((void**)&gattn, g_attn);
    cudaGetSymbolAddress((void**)&wqh, g_wq_hi); cudaGetSymbolAddress((void**)&wql, g_wq_lo);
    cudaGetSymbolAddress((void**)&wkh, g_wk_hi); cudaGetSymbolAddress((void**)&wkl, g_wk_lo);
    cudaGetSymbolAddress((void**)&wvh, g_wv_hi); cudaGetSymbolAddress((void**)&wvl, g_wv_lo);
    cudaGetSymbolAddress((void**)&wph, g_wp_hi); cudaGetSymbolAddress((void**)&wpl, g_wp_lo);

    const int ATTN_SMEM = (64 * 68 + 64 * 72 + 128 * 68) * 4;   // 70656 B
    cudaFuncSetAttribute(attn_tc_kernel,
                         cudaFuncAttributeMaxDynamicSharedMemorySize, ATTN_SMEM);

    // 1. prepack weights (bf16 hi/lo pairs)
    const int PP_N = (D_ / 2) * NDH_;   // 524288
    prepack_w_kernel<<<PP_N / 256, 256>>>(w_q, wqh, wql, D_ / 2, NDH_);
    prepack_w_kernel<<<PP_N / 256, 256>>>(w_k, wkh, wkl, D_ / 2, NDH_);
    prepack_w_kernel<<<PP_N / 256, 256>>>(w_v, wvh, wvl, D_ / 2, NDH_);
    prepack_wpt_kernel<<<PP_N / 256, 256>>>(w_p, wph, wpl);

    // 2. QKV projections, batched in one launch (grid.z selects q/k/v)
    dim3 ggrid(NDH_ / 128, BT_ / 128, 3);   // (8, 32, 3)
    gemm_qkv_kernel<<<ggrid, 256>>>(q_in, k_in, v_in, b_q, b_k, b_v, gq, gk, gv);

    // 3. attention (tf32 tensor core flash attention, 128-row q-tiles)
    dim3 agrid(T_ / 128, B_ * NH_);         // (16, 32)
    attn_tc_kernel<<<agrid, 256, ATTN_SMEM>>>(gq, gk, gv, gattn);

    // 4. output projection
    dim3 pgrid(D_ / 128, BT_ / 128);        // (8, 32)
    gemm_out_kernel<<<pgrid, 256>>>(gattn, b_p, out);
}